// round 3
// baseline (speedup 1.0000x reference)
#include <cuda_runtime.h>
#include <cstdint>
#include <cstddef>

// ---------------- architecture constants ----------------
#define T_STEPS 200
#define BATCH   128
#define N_IN    64
#define N_OUT   10
#define N_ES    512
#define N_ED    1024   // per region
#define REGION  1920
#define N_TOT   3840
#define K_CMP   1792   // compact recurrent K (non-dendrite rows)
#define N_DENDT 2048

#define NB_GEMM 120
#define NB_RO   10
#define NBLK    130

#define DECAY      0.2f
#define ONE_MDECAY 0.8f
#define NOISE_SCALE 0.0063245553203367585f  // sqrt(2*0.2)*0.01

typedef unsigned long long u64;

// ---------------- device scratch (static, no runtime alloc) ----------------
__device__ float g_Wc[(size_t)K_CMP * N_TOT];                  // compacted |w|*mask, [K][N]
__device__ float g_hT[(size_t)N_TOT * BATCH];                  // h, [n][b]
__device__ float g_rcT[2][(size_t)K_CMP * BATCH];              // compact activations, [k][b]
__device__ float g_rdT[2][(size_t)N_DENDT * BATCH];            // dendrite activations, [d][b]
__device__ float g_noiseT[(size_t)T_STEPS * N_TOT * BATCH];    // prescaled noise, [t][n][b]
__device__ float g_xT[(size_t)T_STEPS * N_IN * BATCH];         // input transposed, [t][k][b]
__device__ unsigned g_bar_count;
__device__ unsigned g_bar_gen;

// ---------------- small helpers ----------------
__device__ __forceinline__ void ffma2(u64& d, u64 a, u64 b) {
    asm("fma.rn.f32x2 %0, %1, %2, %0;" : "+l"(d) : "l"(a), "l"(b));
}
__device__ __forceinline__ u64 dup2(float f) {
    u64 r; asm("mov.b64 %0, {%1, %1};" : "=l"(r) : "f"(f)); return r;
}
__device__ __forceinline__ float2 u2f2(u64 v) {
    float2 f; asm("mov.b64 {%0, %1}, %2;" : "=f"(f.x), "=f"(f.y) : "l"(v)); return f;
}

// compact row k -> original neuron index
__device__ __forceinline__ int orig_of_k(int k) {
    int g = k / 896;
    int m = k - g * 896;
    return g * REGION + (m < N_ES ? m : (N_ES + N_ED) + (m - N_ES));
}

// ---------------- preprocessing kernels ----------------
__global__ void prep_wc_kernel(const float* __restrict__ w_rec,
                               const float* __restrict__ mask) {
    size_t idx = (size_t)blockIdx.x * blockDim.x + threadIdx.x;
    size_t total = (size_t)K_CMP * N_TOT;
    if (idx >= total) return;
    int k = (int)(idx / N_TOT);
    int n = (int)(idx - (size_t)k * N_TOT);
    int o = orig_of_k(k);
    size_t src = (size_t)o * N_TOT + n;
    g_Wc[idx] = fabsf(w_rec[src]) * mask[src];
}

__global__ void transpose_noise_kernel(const float* __restrict__ noise) {
    __shared__ float tile[32][33];
    int t  = blockIdx.z;
    int n0 = blockIdx.x * 32;
    int b0 = blockIdx.y * 32;
    #pragma unroll
    for (int i = 0; i < 4; i++) {
        int b = b0 + threadIdx.y + i * 8;
        tile[threadIdx.y + i * 8][threadIdx.x] =
            noise[((size_t)t * BATCH + b) * N_TOT + n0 + threadIdx.x];
    }
    __syncthreads();
    #pragma unroll
    for (int i = 0; i < 4; i++) {
        int n = n0 + threadIdx.y + i * 8;
        g_noiseT[((size_t)t * N_TOT + n) * BATCH + b0 + threadIdx.x] =
            NOISE_SCALE * tile[threadIdx.x][threadIdx.y + i * 8];
    }
}

__global__ void transpose_x_kernel(const float* __restrict__ x) {
    size_t idx = (size_t)blockIdx.x * blockDim.x + threadIdx.x;
    size_t total = (size_t)T_STEPS * BATCH * N_IN;
    if (idx >= total) return;
    int k = (int)(idx % N_IN);
    size_t tb = idx / N_IN;
    int b = (int)(tb % BATCH);
    int t = (int)(tb / BATCH);
    g_xT[((size_t)t * N_IN + k) * BATCH + b] = x[idx];
}

__global__ void init_state_kernel(const float* __restrict__ h0) {
    size_t idx = (size_t)blockIdx.x * blockDim.x + threadIdx.x;
    if (idx >= (size_t)N_TOT * BATCH) return;
    int n = (int)(idx / BATCH);
    int b = (int)(idx - (size_t)n * BATCH);
    float hv = h0[(size_t)b * N_TOT + n];
    g_hT[(size_t)n * BATCH + b] = hv;
    int g = n / REGION;
    int m = n - g * REGION;
    if (m >= N_ES && m < N_ES + N_ED) {
        g_rdT[0][((size_t)(g * N_ED + (m - N_ES))) * BATCH + b] = tanhf(hv);
    } else {
        int c = g * 896 + (m < N_ES ? m : N_ES + (m - (N_ES + N_ED)));
        g_rcT[0][(size_t)c * BATCH + b] = fmaxf(hv, 0.0f);
    }
}

__global__ void reset_barrier_kernel() {
    g_bar_count = 0u;
    g_bar_gen = 0u;
}

// ---------------- grid barrier (all NBLK blocks resident) ----------------
__device__ __forceinline__ void grid_barrier(unsigned gen) {
    __syncthreads();
    if (threadIdx.x == 0) {
        __threadfence();                         // release + own-L1 invalidate
        unsigned arrived = atomicAdd(&g_bar_count, 1u);
        if (arrived == NBLK - 1u) {
            g_bar_count = 0u;
            __threadfence();
            asm volatile("st.release.gpu.u32 [%0], %1;"
                         :: "l"(&g_bar_gen), "r"(gen + 1u) : "memory");
        } else {
            unsigned cur;
            do {
                __nanosleep(64);
                asm volatile("ld.acquire.gpu.u32 %0, [%1];"
                             : "=r"(cur) : "l"(&g_bar_gen) : "memory");
            } while (cur == gen);
        }
    }
    __syncthreads();
}

// ---------------- persistent rollout kernel ----------------
// blocks 0..119: GEMM + state update for 32 columns each
// blocks 120..129: readout (one output column each), pipelined one step behind
__global__ void __launch_bounds__(128, 1)
rollout_kernel(const float* __restrict__ w_in,
               const float* __restrict__ bias,
               const float* __restrict__ w_out,
               float* __restrict__ out) {
    __shared__ __align__(16) float wsd[2][16][64];   // dup-pair W tiles
    __shared__ __align__(16) float rs[2][16][128];   // r tiles
    __shared__ float wcol[N_ES];                     // readout weights

    const int tid = threadIdx.x;
    const int bx  = blockIdx.x;
    unsigned mygen = 0;

    if (bx < NB_GEMM) {
        const int tx = tid & 7;          // col quad
        const int ty = tid >> 3;         // batch octet
        const int b0 = ty * 8;
        const int nblock = bx * 32;
        const int wkk = tid >> 3, wq = tid & 7;
        int kkr[4], bq[4];
        #pragma unroll
        for (int i = 0; i < 4; i++) {
            int idx = tid + i * 128;
            kkr[i] = idx >> 5;
            bq[i]  = (idx & 31) * 4;
        }
        const int g = nblock / REGION;
        const int m = nblock - g * REGION;
        const bool isDend = (m >= N_ES && m < N_ES + N_ED);
        const bool isES   = (m < N_ES);

        for (int t = 0; t < T_STEPS; t++) {
            const int pr = t & 1, pw = (t + 1) & 1;
            const float* __restrict__ rprev = g_rcT[pr];

            u64 acc2[4][4];
            #pragma unroll
            for (int i = 0; i < 4; i++)
                #pragma unroll
                for (int j = 0; j < 4; j++) acc2[i][j] = 0ull;

            // ---- prologue: chunk 0 ----
            float4 wn = *(const float4*)&g_Wc[(size_t)wkk * N_TOT + nblock + wq * 4];
            float4 rn[4];
            #pragma unroll
            for (int i = 0; i < 4; i++)
                rn[i] = *(const float4*)&rprev[(size_t)kkr[i] * BATCH + bq[i]];
            {   // stage buf 0
                float4 lo = make_float4(wn.x, wn.x, wn.y, wn.y);
                float4 hi = make_float4(wn.z, wn.z, wn.w, wn.w);
                *(float4*)&wsd[0][wkk][wq * 8]     = lo;
                *(float4*)&wsd[0][wkk][wq * 8 + 4] = hi;
                #pragma unroll
                for (int i = 0; i < 4; i++)
                    *(float4*)&rs[0][kkr[i]][bq[i]] = rn[i];
            }
            __syncthreads();

            // ---- main K loop: 112 chunks of 16 ----
            #pragma unroll 1
            for (int kc = 0; kc < K_CMP / 16; kc++) {
                const int cur = kc & 1;
                const bool more = (kc + 1) < K_CMP / 16;
                if (more) {
                    const int k0 = (kc + 1) * 16;
                    wn = *(const float4*)&g_Wc[(size_t)(k0 + wkk) * N_TOT + nblock + wq * 4];
                    #pragma unroll
                    for (int i = 0; i < 4; i++)
                        rn[i] = *(const float4*)&rprev[(size_t)(k0 + kkr[i]) * BATCH + bq[i]];
                }
                const float* wbuf = &wsd[cur][0][0];
                const float* rbuf = &rs[cur][0][0];
                #pragma unroll
                for (int kk = 0; kk < 16; kk++) {
                    ulonglong2 w01 = *(const ulonglong2*)&wbuf[kk * 64 + tx * 8];
                    ulonglong2 w23 = *(const ulonglong2*)&wbuf[kk * 64 + tx * 8 + 4];
                    ulonglong2 rA  = *(const ulonglong2*)&rbuf[kk * 128 + b0];
                    ulonglong2 rB  = *(const ulonglong2*)&rbuf[kk * 128 + b0 + 4];
                    ffma2(acc2[0][0], rA.x, w01.x); ffma2(acc2[0][1], rA.x, w01.y);
                    ffma2(acc2[0][2], rA.x, w23.x); ffma2(acc2[0][3], rA.x, w23.y);
                    ffma2(acc2[1][0], rA.y, w01.x); ffma2(acc2[1][1], rA.y, w01.y);
                    ffma2(acc2[1][2], rA.y, w23.x); ffma2(acc2[1][3], rA.y, w23.y);
                    ffma2(acc2[2][0], rB.x, w01.x); ffma2(acc2[2][1], rB.x, w01.y);
                    ffma2(acc2[2][2], rB.x, w23.x); ffma2(acc2[2][3], rB.x, w23.y);
                    ffma2(acc2[3][0], rB.y, w01.x); ffma2(acc2[3][1], rB.y, w01.y);
                    ffma2(acc2[3][2], rB.y, w23.x); ffma2(acc2[3][3], rB.y, w23.y);
                }
                __syncthreads();
                if (more) {
                    const int nxt = 1 - cur;
                    float4 lo = make_float4(wn.x, wn.x, wn.y, wn.y);
                    float4 hi = make_float4(wn.z, wn.z, wn.w, wn.w);
                    *(float4*)&wsd[nxt][wkk][wq * 8]     = lo;
                    *(float4*)&wsd[nxt][wkk][wq * 8 + 4] = hi;
                    #pragma unroll
                    for (int i = 0; i < 4; i++)
                        *(float4*)&rs[nxt][kkr[i]][bq[i]] = rn[i];
                }
                __syncthreads();
            }

            // ---- input contribution: x_t @ w_in, K = 64 ----
            const float* __restrict__ xt = &g_xT[(size_t)t * N_IN * BATCH];
            #pragma unroll 4
            for (int k2 = 0; k2 < N_IN; k2++) {
                float4 w = *(const float4*)&w_in[(size_t)k2 * N_TOT + nblock + tx * 4];
                u64 wd0 = dup2(w.x), wd1 = dup2(w.y), wd2 = dup2(w.z), wd3 = dup2(w.w);
                ulonglong2 xA = *(const ulonglong2*)&xt[k2 * BATCH + b0];
                ulonglong2 xB = *(const ulonglong2*)&xt[k2 * BATCH + b0 + 4];
                ffma2(acc2[0][0], xA.x, wd0); ffma2(acc2[0][1], xA.x, wd1);
                ffma2(acc2[0][2], xA.x, wd2); ffma2(acc2[0][3], xA.x, wd3);
                ffma2(acc2[1][0], xA.y, wd0); ffma2(acc2[1][1], xA.y, wd1);
                ffma2(acc2[1][2], xA.y, wd2); ffma2(acc2[1][3], xA.y, wd3);
                ffma2(acc2[2][0], xB.x, wd0); ffma2(acc2[2][1], xB.x, wd1);
                ffma2(acc2[2][2], xB.x, wd2); ffma2(acc2[2][3], xB.x, wd3);
                ffma2(acc2[3][0], xB.y, wd0); ffma2(acc2[3][1], xB.y, wd1);
                ffma2(acc2[3][2], xB.y, wd2); ffma2(acc2[3][3], xB.y, wd3);
            }

            // ---- epilogue ----
            #pragma unroll
            for (int j = 0; j < 4; j++) {
                const int n  = nblock + tx * 4 + j;
                const int mm = m + tx * 4 + j;
                const float bv = bias[n];
                const size_t hbase = (size_t)n * BATCH;
                const size_t nz = ((size_t)t * N_TOT + n) * BATCH;
                const float* __restrict__ d0 =
                    isES ? &g_rdT[pr][(size_t)(g * N_ED + mm) * BATCH] : nullptr;
                const float* __restrict__ d1 =
                    isES ? &g_rdT[pr][(size_t)(g * N_ED + N_ES + mm) * BATCH] : nullptr;
                float* __restrict__ rout;
                if (isDend) rout = &g_rdT[pw][(size_t)(g * N_ED + (mm - N_ES)) * BATCH];
                else {
                    int c = g * 896 + (isES ? mm : N_ES + (mm - (N_ES + N_ED)));
                    rout = &g_rcT[pw][(size_t)c * BATCH];
                }
                #pragma unroll
                for (int bp = 0; bp < 4; bp++) {
                    float2 v = u2f2(acc2[bp][j]);
                    #pragma unroll
                    for (int l = 0; l < 2; l++) {
                        const int b = b0 + bp * 2 + l;
                        float tot = (l == 0 ? v.x : v.y) + bv;
                        if (isES) tot += d0[b] + d1[b];
                        float hn = ONE_MDECAY * g_hT[hbase + b] + DECAY * tot + g_noiseT[nz + b];
                        g_hT[hbase + b] = hn;
                        rout[b] = isDend ? tanhf(hn) : fmaxf(hn, 0.0f);
                    }
                }
            }

            grid_barrier(mygen);
            mygen++;
        }
    } else {
        // ---- readout blocks: one output column each, one step behind ----
        const int o = bx - NB_GEMM;
        for (int s = tid; s < N_ES; s += 128)
            wcol[s] = w_out[(size_t)s * N_OUT + o];
        __syncthreads();

        for (int t = 0; t < T_STEPS; t++) {
            if (t > 0) {
                const int tt = t - 1;
                const float* __restrict__ r = g_rcT[(tt + 1) & 1];
                float accv = 0.0f;
                #pragma unroll 8
                for (int s = 0; s < N_ES; s++)
                    accv += r[(size_t)s * BATCH + tid] * wcol[s];
                out[((size_t)tt * BATCH + tid) * N_OUT + o] = accv;
            }
            grid_barrier(mygen);
            mygen++;
        }
        {   // final step readout
            const int tt = T_STEPS - 1;
            const float* __restrict__ r = g_rcT[(tt + 1) & 1];
            float accv = 0.0f;
            #pragma unroll 8
            for (int s = 0; s < N_ES; s++)
                accv += r[(size_t)s * BATCH + tid] * wcol[s];
            out[((size_t)tt * BATCH + tid) * N_OUT + o] = accv;
        }
    }
}

// ---------------- launch ----------------
extern "C" void kernel_launch(void* const* d_in, const int* in_sizes, int n_in,
                              void* d_out, int out_size) {
    const float* x     = (const float*)d_in[0];
    const float* noise = (const float*)d_in[1];
    const float* w_rec = (const float*)d_in[2];
    const float* w_in  = (const float*)d_in[3];
    const float* w_out = (const float*)d_in[4];
    const float* bias  = (const float*)d_in[5];
    const float* h0    = (const float*)d_in[6];
    const float* mask  = (const float*)d_in[7];
    float* out = (float*)d_out;
    (void)in_sizes; (void)n_in; (void)out_size;

    {
        size_t total = (size_t)K_CMP * N_TOT;
        prep_wc_kernel<<<(int)((total + 255) / 256), 256>>>(w_rec, mask);
    }
    {
        dim3 grid(N_TOT / 32, BATCH / 32, T_STEPS);
        dim3 block(32, 8);
        transpose_noise_kernel<<<grid, block>>>(noise);
    }
    {
        size_t total = (size_t)T_STEPS * BATCH * N_IN;
        transpose_x_kernel<<<(int)((total + 255) / 256), 256>>>(x);
    }
    {
        size_t total = (size_t)N_TOT * BATCH;
        init_state_kernel<<<(int)((total + 255) / 256), 256>>>(h0);
    }
    reset_barrier_kernel<<<1, 1>>>();

    rollout_kernel<<<NBLK, 128>>>(w_in, bias, w_out, out);
}

// round 9
// speedup vs baseline: 1.7756x; 1.7756x over previous
#include <cuda_runtime.h>
#include <cuda_bf16.h>
#include <cstdint>
#include <cstddef>

#define T_STEPS 200
#define BATCH 128
#define N_IN 64
#define N_OUT 10
#define N_ES 512
#define REGION 1920
#define N_TOT 3840
#define K_CMP 1792
#define NB_GEMM 120
#define NBLK 130
#define CH_TOT 29            /* 28 recurrent K64 chunks + 1 input chunk */
#define DECAY 0.2f
#define NOISE_SCALE 0.0063245553203367585f

#define STAGE_BYTES 49152
#define A_HI 0
#define A_MI 8192
#define A_LO 16384
#define B_HI 24576
#define B_MI 32768
#define B_LO 40960
#define DSM_OFF 147456       /* 64 x 72 floats = 18432 B */
#define BIAS_OFF 165888
#define SMEM_DYN 166400

typedef unsigned long long u64;
typedef __nv_bfloat16 bf16;

__device__ __align__(16) bf16  g_WtHi[(size_t)N_TOT * K_CMP];
__device__ __align__(16) bf16  g_WtMi[(size_t)N_TOT * K_CMP];
__device__ __align__(16) bf16  g_WtLo[(size_t)N_TOT * K_CMP];
__device__ __align__(16) bf16  g_WinHi[(size_t)N_TOT * N_IN];
__device__ __align__(16) bf16  g_WinMi[(size_t)N_TOT * N_IN];
__device__ __align__(16) bf16  g_WinLo[(size_t)N_TOT * N_IN];
__device__ __align__(16) bf16  g_xHi[(size_t)T_STEPS * BATCH * N_IN];
__device__ __align__(16) bf16  g_xMi[(size_t)T_STEPS * BATCH * N_IN];
__device__ __align__(16) bf16  g_xLo[(size_t)T_STEPS * BATCH * N_IN];
__device__ __align__(16) bf16  g_rHi[2][(size_t)BATCH * K_CMP];
__device__ __align__(16) bf16  g_rMi[2][(size_t)BATCH * K_CMP];
__device__ __align__(16) bf16  g_rLo[2][(size_t)BATCH * K_CMP];
__device__ __align__(16) float g_rd[2][(size_t)BATCH * 2048];
__device__ __align__(16) float g_h[(size_t)BATCH * N_TOT];
__device__ unsigned g_bar_count, g_bar_gen;

__device__ __forceinline__ uint32_t smem_u32(const void* p) {
    uint32_t a;
    asm("{ .reg .u64 t; cvta.to.shared.u64 t, %1; cvt.u32.u64 %0, t; }" : "=r"(a) : "l"(p));
    return a;
}
#define SWZ(o) ((o) ^ (((o) >> 3) & 0x70))
__device__ __forceinline__ void cp16(uint32_t d, const void* s) {
    asm volatile("cp.async.cg.shared.global [%0], [%1], 16;" :: "r"(d), "l"(s));
}
#define LDSM4(r0, r1, r2, r3, a) \
    asm volatile("ldmatrix.sync.aligned.m8n8.x4.shared.b16 {%0,%1,%2,%3}, [%4];" \
                 : "=r"(r0), "=r"(r1), "=r"(r2), "=r"(r3) : "r"(a))
#define MMA(d, a, b) \
    asm volatile("mma.sync.aligned.m16n8k16.row.col.f32.bf16.bf16.f32 " \
                 "{%0,%1,%2,%3},{%4,%5,%6,%7},{%8,%9},{%0,%1,%2,%3};" \
                 : "+f"((d)[0]), "+f"((d)[1]), "+f"((d)[2]), "+f"((d)[3]) \
                 : "r"((a)[0]), "r"((a)[1]), "r"((a)[2]), "r"((a)[3]), \
                   "r"((b)[0]), "r"((b)[1]))

__device__ __forceinline__ void split3(float v, bf16& h, bf16& m, bf16& l) {
    h = __float2bfloat16(v);
    float r1 = v - __bfloat162float(h);
    m = __float2bfloat16(r1);
    l = __float2bfloat16(r1 - __bfloat162float(m));
}
__device__ __forceinline__ int korig_add(int k) {
    return (k < 512) ? 0 : (k < 1408 ? 1024 : 2048);
}

// ---------- preprocessing ----------
__global__ void prep_w_kernel(const float* __restrict__ w_rec, const float* __restrict__ mask) {
    __shared__ float tile[32][33];
    int k0 = blockIdx.x * 32, n0 = blockIdx.y * 32;
    int orig0 = k0 + korig_add(k0);
    #pragma unroll
    for (int i = 0; i < 4; i++) {
        int r = threadIdx.y + i * 8;
        size_t s = (size_t)(orig0 + r) * N_TOT + n0 + threadIdx.x;
        tile[r][threadIdx.x] = fabsf(w_rec[s]) * mask[s];
    }
    __syncthreads();
    #pragma unroll
    for (int i = 0; i < 4; i++) {
        int rr = threadIdx.y + i * 8;
        float v = tile[threadIdx.x][rr];
        bf16 h, m, l;
        split3(v, h, m, l);
        size_t d = (size_t)(n0 + rr) * K_CMP + k0 + threadIdx.x;
        g_WtHi[d] = h; g_WtMi[d] = m; g_WtLo[d] = l;
    }
}
__global__ void prep_win_kernel(const float* __restrict__ w_in) {
    size_t i = (size_t)blockIdx.x * blockDim.x + threadIdx.x;
    if (i >= (size_t)N_IN * N_TOT) return;
    int kin = (int)(i / N_TOT), n = (int)(i - (size_t)kin * N_TOT);
    bf16 h, m, l;
    split3(w_in[i], h, m, l);
    size_t d = (size_t)n * N_IN + kin;
    g_WinHi[d] = h; g_WinMi[d] = m; g_WinLo[d] = l;
}
__global__ void prep_x_kernel(const float* __restrict__ x) {
    size_t i = (size_t)blockIdx.x * blockDim.x + threadIdx.x;
    if (i >= (size_t)T_STEPS * BATCH * N_IN) return;
    bf16 h, m, l;
    split3(x[i], h, m, l);
    g_xHi[i] = h; g_xMi[i] = m; g_xLo[i] = l;
}
__global__ void init_state_kernel(const float* __restrict__ h0) {
    size_t i = (size_t)blockIdx.x * blockDim.x + threadIdx.x;
    if (i >= (size_t)BATCH * N_TOT) return;
    int n = (int)(i % N_TOT), b = (int)(i / N_TOT);
    float hv = h0[i];
    g_h[i] = hv;
    int g = n / REGION, m = n - g * REGION;
    if (m >= 512 && m < 1536) {
        g_rd[0][(size_t)b * 2048 + g * 1024 + (m - 512)] = tanhf(hv);
    } else {
        float r = fmaxf(hv, 0.f);
        int k = g * 896 + (m < 512 ? m : 512 + (m - 1536));
        bf16 hh, mm, ll;
        split3(r, hh, mm, ll);
        size_t d = (size_t)b * K_CMP + k;
        g_rHi[0][d] = hh; g_rMi[0][d] = mm; g_rLo[0][d] = ll;
    }
}
__global__ void reset_barrier_kernel() { g_bar_count = 0u; g_bar_gen = 0u; }

__device__ __forceinline__ void grid_barrier(unsigned gen) {
    __syncthreads();
    if (threadIdx.x == 0) {
        __threadfence();
        if (atomicAdd(&g_bar_count, 1u) == NBLK - 1u) {
            g_bar_count = 0u;
            __threadfence();
            asm volatile("st.release.gpu.u32 [%0], %1;" :: "l"(&g_bar_gen), "r"(gen + 1u) : "memory");
        } else {
            unsigned cur;
            do {
                __nanosleep(64);
                asm volatile("ld.acquire.gpu.u32 %0, [%1];" : "=r"(cur) : "l"(&g_bar_gen) : "memory");
            } while (cur == gen);
        }
    }
    __syncthreads();
}

// one K64 chunk into stage stg: A 64x128B (hi,mi,lo) + B 64x128B (hi,mi,lo)
__device__ __forceinline__ void load_chunk(uint32_t sb, int stg, int c, int t,
                                           int mt, int b0, int pr, int tid) {
    uint32_t st = sb + stg * STAGE_BYTES;
    int row = tid >> 1, s0 = (tid & 1) * 4;
    const bf16 *Ah, *Am, *Al, *Bh, *Bm, *Bl;
    if (c < CH_TOT - 1) {
        size_t ao = (size_t)(mt * 64 + row) * K_CMP + c * 64;
        Ah = g_WtHi + ao; Am = g_WtMi + ao; Al = g_WtLo + ao;
        size_t bo = (size_t)(b0 + row) * K_CMP + c * 64;
        Bh = g_rHi[pr] + bo; Bm = g_rMi[pr] + bo; Bl = g_rLo[pr] + bo;
    } else {
        size_t ao = (size_t)(mt * 64 + row) * N_IN;
        Ah = g_WinHi + ao; Am = g_WinMi + ao; Al = g_WinLo + ao;
        size_t bo = ((size_t)t * BATCH + b0 + row) * N_IN;
        Bh = g_xHi + bo; Bm = g_xMi + bo; Bl = g_xLo + bo;
    }
    #pragma unroll
    for (int i = 0; i < 4; i++) {
        int s = s0 + i;
        uint32_t d = SWZ((uint32_t)(row * 128 + s * 16));
        cp16(st + A_HI + d, Ah + s * 8);
        cp16(st + A_MI + d, Am + s * 8);
        cp16(st + A_LO + d, Al + s * 8);
        cp16(st + B_HI + d, Bh + s * 8);
        cp16(st + B_MI + d, Bm + s * 8);
        cp16(st + B_LO + d, Bl + s * 8);
    }
    asm volatile("cp.async.commit_group;" ::: "memory");
}

__global__ void __launch_bounds__(128, 1)
rollout_kernel(const float* __restrict__ noise, const float* __restrict__ bias,
               const float* __restrict__ w_out, float* __restrict__ out) {
    extern __shared__ __align__(1024) char sm[];
    uint32_t sb = smem_u32(sm);
    const int tid = threadIdx.x, bx = blockIdx.x;
    unsigned gen = 0;

    if (bx < NB_GEMM) {
        const int mt = bx >> 1, b0 = (bx & 1) * 64;
        const int n0t = mt * 64;
        const int g = n0t / REGION, m0 = n0t - g * REGION;
        const bool isES = (m0 < 512), isDend = (m0 >= 512 && m0 < 1536);
        float* dsm = (float*)(sm + DSM_OFF);
        float* bias_s = (float*)(sm + BIAS_OFF);

        const int wid = tid >> 5, lane = tid & 31;
        const int mw = (wid >> 1) * 32, nw = (wid & 1) * 32;
        const int g8 = lane >> 3, r8 = lane & 7;
        const int aRow = mw + (g8 & 1) * 8 + r8;
        const uint32_t aKh = (uint32_t)((g8 >> 1) * 16);
        const uint32_t aXor = (uint32_t)((aRow & 7) * 16);
        const uint32_t aB0 = (uint32_t)(aRow * 128);
        const int bRow = nw + (g8 >> 1) * 8 + r8;
        const uint32_t bKh = (uint32_t)((g8 & 1) * 16);
        const uint32_t bXor = (uint32_t)((bRow & 7) * 16);
        const uint32_t bB0 = (uint32_t)(bRow * 128);

        if (tid < 64) bias_s[tid] = bias[n0t + tid];
        __syncthreads();

        for (int t = 0; t < T_STEPS; t++) {
            const int pr = t & 1, pw = 1 - pr;
            float acc[2][4][4];   // Kahan running sum
            float cmp[2][4][4];   // Kahan compensation
            #pragma unroll
            for (int a = 0; a < 2; a++)
                #pragma unroll
                for (int c = 0; c < 4; c++)
                    #pragma unroll
                    for (int d = 0; d < 4; d++) { acc[a][c][d] = 0.f; cmp[a][c][d] = 0.f; }

            load_chunk(sb, 0, 0, t, mt, b0, pr, tid);
            load_chunk(sb, 1, 1, t, mt, b0, pr, tid);
            #pragma unroll 1
            for (int c = 0; c < CH_TOT; c++) {
                if (c + 2 < CH_TOT) {
                    load_chunk(sb, (c + 2) % 3, c + 2, t, mt, b0, pr, tid);
                    asm volatile("cp.async.wait_group 2;" ::: "memory");
                } else if (c + 1 < CH_TOT) {
                    asm volatile("cp.async.wait_group 1;" ::: "memory");
                } else {
                    asm volatile("cp.async.wait_group 0;" ::: "memory");
                }
                __syncthreads();
                uint32_t st = sb + (uint32_t)(c % 3) * STAGE_BYTES;

                // fresh chunk accumulator: keeps per-MMA rounding at chunk scale
                float sub[2][4][4];
                #pragma unroll
                for (int a = 0; a < 2; a++)
                    #pragma unroll
                    for (int cc = 0; cc < 4; cc++)
                        #pragma unroll
                        for (int d = 0; d < 4; d++) sub[a][cc][d] = 0.f;

                #pragma unroll
                for (int ks = 0; ks < 4; ks++) {
                    const uint32_t ka = ((uint32_t)(ks * 32) + aKh) ^ aXor;
                    const uint32_t kb = ((uint32_t)(ks * 32) + bKh) ^ bXor;
                    uint32_t ah[2][4], am[2][4], al[2][4];
                    uint32_t bh[2][4], bm[2][4], bl[2][4];
                    #pragma unroll
                    for (int mb = 0; mb < 2; mb++) {
                        uint32_t ra = st + aB0 + (uint32_t)(mb * 16 * 128) + ka;
                        LDSM4(ah[mb][0], ah[mb][1], ah[mb][2], ah[mb][3], ra + A_HI);
                        LDSM4(am[mb][0], am[mb][1], am[mb][2], am[mb][3], ra + A_MI);
                        LDSM4(al[mb][0], al[mb][1], al[mb][2], al[mb][3], ra + A_LO);
                    }
                    #pragma unroll
                    for (int nb = 0; nb < 2; nb++) {
                        uint32_t rb = st + bB0 + (uint32_t)(nb * 16 * 128) + kb;
                        LDSM4(bh[nb][0], bh[nb][1], bh[nb][2], bh[nb][3], rb + B_HI);
                        LDSM4(bm[nb][0], bm[nb][1], bm[nb][2], bm[nb][3], rb + B_MI);
                        LDSM4(bl[nb][0], bl[nb][1], bl[nb][2], bl[nb][3], rb + B_LO);
                    }
                    #pragma unroll
                    for (int mb = 0; mb < 2; mb++)
                        #pragma unroll
                        for (int nb = 0; nb < 2; nb++)
                            #pragma unroll
                            for (int h = 0; h < 2; h++) {
                                float* d = sub[mb][nb * 2 + h];
                                MMA(d, ah[mb], &bh[nb][h * 2]);   // hh
                                MMA(d, ah[mb], &bm[nb][h * 2]);   // hm
                                MMA(d, am[mb], &bh[nb][h * 2]);   // mh
                                MMA(d, ah[mb], &bl[nb][h * 2]);   // hl
                                MMA(d, am[mb], &bm[nb][h * 2]);   // mm
                                MMA(d, al[mb], &bh[nb][h * 2]);   // lh
                            }
                }

                // Kahan-fold chunk accumulator into running total
                #pragma unroll
                for (int a = 0; a < 2; a++)
                    #pragma unroll
                    for (int cc = 0; cc < 4; cc++)
                        #pragma unroll
                        for (int d = 0; d < 4; d++) {
                            float y = sub[a][cc][d] - cmp[a][cc][d];
                            float tt = acc[a][cc][d] + y;
                            cmp[a][cc][d] = (tt - acc[a][cc][d]) - y;
                            acc[a][cc][d] = tt;
                        }
                __syncthreads();
            }

            // fragments -> dsm[n][b] (stride 72)
            {
                const int mr = lane >> 2, bc = (lane & 3) * 2;
                #pragma unroll
                for (int mb = 0; mb < 2; mb++)
                    #pragma unroll
                    for (int nf = 0; nf < 4; nf++) {
                        int m = mw + mb * 16 + mr;
                        int bcol = nw + nf * 8 + bc;
                        *(float2*)&dsm[m * 72 + bcol] =
                            make_float2(acc[mb][nf][0], acc[mb][nf][1]);
                        *(float2*)&dsm[(m + 8) * 72 + bcol] =
                            make_float2(acc[mb][nf][2], acc[mb][nf][3]);
                    }
            }
            __syncthreads();

            // ---- epilogue: batch-major state update ----
            {
                const int bl2 = tid & 63, hf = tid >> 6;
                const int b = b0 + bl2, nl0 = hf * 32;
                float* __restrict__ hp = g_h + (size_t)b * N_TOT + n0t + nl0;
                const float* __restrict__ nz =
                    noise + ((size_t)t * BATCH + b) * N_TOT + n0t + nl0;
                const float* __restrict__ d0 = isES ?
                    g_rd[pr] + (size_t)b * 2048 + g * 1024 + (m0 + nl0) : nullptr;
                const float* __restrict__ d1 = isES ? d0 + 512 : nullptr;
                float* __restrict__ rdw = isDend ?
                    g_rd[pw] + (size_t)b * 2048 + g * 1024 + (m0 - 512) + nl0 : nullptr;
                const int k0 = g * 896 + (m0 < 512 ? m0 : 512 + (m0 - 1536)) + nl0;
                bf16* __restrict__ rhw = g_rHi[pw] + (size_t)b * K_CMP + k0;
                bf16* __restrict__ rmw = g_rMi[pw] + (size_t)b * K_CMP + k0;
                bf16* __restrict__ rlw = g_rLo[pw] + (size_t)b * K_CMP + k0;
                #pragma unroll 4
                for (int i = 0; i < 32; i += 4) {
                    float4 hv = *(const float4*)&hp[i];
                    float4 nv = *(const float4*)&nz[i];
                    float tv[4], hn[4];
                    #pragma unroll
                    for (int j = 0; j < 4; j++)
                        tv[j] = dsm[(nl0 + i + j) * 72 + bl2] + bias_s[nl0 + i + j];
                    if (isES) {
                        float4 a0 = *(const float4*)&d0[i];
                        float4 a1 = *(const float4*)&d1[i];
                        tv[0] += a0.x + a1.x; tv[1] += a0.y + a1.y;
                        tv[2] += a0.z + a1.z; tv[3] += a0.w + a1.w;
                    }
                    hn[0] = 0.8f * hv.x + DECAY * tv[0] + NOISE_SCALE * nv.x;
                    hn[1] = 0.8f * hv.y + DECAY * tv[1] + NOISE_SCALE * nv.y;
                    hn[2] = 0.8f * hv.z + DECAY * tv[2] + NOISE_SCALE * nv.z;
                    hn[3] = 0.8f * hv.w + DECAY * tv[3] + NOISE_SCALE * nv.w;
                    *(float4*)&hp[i] = make_float4(hn[0], hn[1], hn[2], hn[3]);
                    if (isDend) {
                        *(float4*)&rdw[i] = make_float4(tanhf(hn[0]), tanhf(hn[1]),
                                                        tanhf(hn[2]), tanhf(hn[3]));
                    } else {
                        uint32_t hw[2], mw2[2], lw[2];
                        #pragma unroll
                        for (int p = 0; p < 2; p++) {
                            float r0 = fmaxf(hn[p * 2], 0.f), r1 = fmaxf(hn[p * 2 + 1], 0.f);
                            bf16 h0b, m0b, l0b, h1b, m1b, l1b;
                            split3(r0, h0b, m0b, l0b);
                            split3(r1, h1b, m1b, l1b);
                            hw[p] = (uint32_t)__bfloat16_as_ushort(h0b) |
                                    ((uint32_t)__bfloat16_as_ushort(h1b) << 16);
                            mw2[p] = (uint32_t)__bfloat16_as_ushort(m0b) |
                                     ((uint32_t)__bfloat16_as_ushort(m1b) << 16);
                            lw[p] = (uint32_t)__bfloat16_as_ushort(l0b) |
                                    ((uint32_t)__bfloat16_as_ushort(l1b) << 16);
                        }
                        *(uint2*)&rhw[i] = make_uint2(hw[0], hw[1]);
                        *(uint2*)&rmw[i] = make_uint2(mw2[0], mw2[1]);
                        *(uint2*)&rlw[i] = make_uint2(lw[0], lw[1]);
                    }
                }
            }
            grid_barrier(gen); gen++;
        }
    } else {
        const int o = bx - NB_GEMM;
        float* wcol = (float*)sm;
        for (int s = tid; s < N_ES; s += 128) wcol[s] = w_out[(size_t)s * N_OUT + o];
        __syncthreads();
        for (int t = 0; t <= T_STEPS; t++) {
            if (t > 0) {
                const int tt = t - 1, buf = (tt + 1) & 1;
                const bf16* __restrict__ rh = g_rHi[buf] + (size_t)tid * K_CMP;
                const bf16* __restrict__ rm = g_rMi[buf] + (size_t)tid * K_CMP;
                const bf16* __restrict__ rl = g_rLo[buf] + (size_t)tid * K_CMP;
                float acc = 0.f;
                #pragma unroll 8
                for (int s = 0; s < N_ES; s++)
                    acc += (__bfloat162float(rh[s]) + __bfloat162float(rm[s])
                            + __bfloat162float(rl[s])) * wcol[s];
                out[((size_t)tt * BATCH + tid) * N_OUT + o] = acc;
            }
            if (t < T_STEPS) { grid_barrier(gen); gen++; }
        }
    }
}

extern "C" void kernel_launch(void* const* d_in, const int* in_sizes, int n_in,
                              void* d_out, int out_size) {
    const float* x     = (const float*)d_in[0];
    const float* noise = (const float*)d_in[1];
    const float* w_rec = (const float*)d_in[2];
    const float* w_in  = (const float*)d_in[3];
    const float* w_out = (const float*)d_in[4];
    const float* bias  = (const float*)d_in[5];
    const float* h0    = (const float*)d_in[6];
    const float* mask  = (const float*)d_in[7];
    float* out = (float*)d_out;
    (void)in_sizes; (void)n_in; (void)out_size;

    cudaFuncSetAttribute(rollout_kernel, cudaFuncAttributeMaxDynamicSharedMemorySize, SMEM_DYN);

    { dim3 g(K_CMP / 32, N_TOT / 32); prep_w_kernel<<<g, dim3(32, 8)>>>(w_rec, mask); }
    { size_t n = (size_t)N_IN * N_TOT; prep_win_kernel<<<(int)((n + 255) / 256), 256>>>(w_in); }
    { size_t n = (size_t)T_STEPS * BATCH * N_IN; prep_x_kernel<<<(int)((n + 255) / 256), 256>>>(x); }
    { size_t n = (size_t)BATCH * N_TOT; init_state_kernel<<<(int)((n + 255) / 256), 256>>>(h0); }
    reset_barrier_kernel<<<1, 1>>>();

    rollout_kernel<<<NBLK, 128, SMEM_DYN>>>(noise, bias, w_out, out);
}

// round 11
// speedup vs baseline: 1.7844x; 1.0050x over previous
#include <cuda_runtime.h>
#include <cuda_bf16.h>
#include <cstdint>
#include <cstddef>

#define T_STEPS 200
#define BATCH 128
#define N_IN 64
#define N_OUT 10
#define N_ES 512
#define REGION 1920
#define N_TOT 3840
#define K_CMP 1792
#define NB_GEMM 120
#define NBLK 130
#define CH_TOT 29            /* 28 recurrent K64 chunks + 1 input chunk */
#define DECAY 0.2f
#define NOISE_SCALE 0.0063245553203367585f

#define STAGE_BYTES 49152
#define A_HI 0
#define A_MI 8192
#define A_LO 16384
#define B_HI 24576
#define B_MI 32768
#define B_LO 40960
#define DSM_OFF 147456       /* 64 x 72 floats = 18432 B */
#define BIAS_OFF 165888
#define SMEM_DYN 166400

typedef unsigned long long u64;
typedef __nv_bfloat16 bf16;

__device__ __align__(16) bf16  g_WtHi[(size_t)N_TOT * K_CMP];
__device__ __align__(16) bf16  g_WtMi[(size_t)N_TOT * K_CMP];
__device__ __align__(16) bf16  g_WtLo[(size_t)N_TOT * K_CMP];
__device__ __align__(16) bf16  g_WinHi[(size_t)N_TOT * N_IN];
__device__ __align__(16) bf16  g_WinMi[(size_t)N_TOT * N_IN];
__device__ __align__(16) bf16  g_WinLo[(size_t)N_TOT * N_IN];
__device__ __align__(16) bf16  g_xHi[(size_t)T_STEPS * BATCH * N_IN];
__device__ __align__(16) bf16  g_xMi[(size_t)T_STEPS * BATCH * N_IN];
__device__ __align__(16) bf16  g_xLo[(size_t)T_STEPS * BATCH * N_IN];
__device__ __align__(16) bf16  g_rHi[2][(size_t)BATCH * K_CMP];
__device__ __align__(16) bf16  g_rMi[2][(size_t)BATCH * K_CMP];
__device__ __align__(16) bf16  g_rLo[2][(size_t)BATCH * K_CMP];
__device__ __align__(16) float g_rd[2][(size_t)BATCH * 2048];
__device__ __align__(16) float g_h[(size_t)BATCH * N_TOT];
__device__ unsigned g_bar_count, g_bar_gen;

__device__ __forceinline__ uint32_t smem_u32(const void* p) {
    uint32_t a;
    asm("{ .reg .u64 t; cvta.to.shared.u64 t, %1; cvt.u32.u64 %0, t; }" : "=r"(a) : "l"(p));
    return a;
}
#define SWZ(o) ((o) ^ (((o) >> 3) & 0x70))
__device__ __forceinline__ void cp16(uint32_t d, const void* s) {
    asm volatile("cp.async.cg.shared.global [%0], [%1], 16;" :: "r"(d), "l"(s));
}
#define LDSM4(r0, r1, r2, r3, a) \
    asm volatile("ldmatrix.sync.aligned.m8n8.x4.shared.b16 {%0,%1,%2,%3}, [%4];" \
                 : "=r"(r0), "=r"(r1), "=r"(r2), "=r"(r3) : "r"(a))
#define MMA(d, a, b) \
    asm volatile("mma.sync.aligned.m16n8k16.row.col.f32.bf16.bf16.f32 " \
                 "{%0,%1,%2,%3},{%4,%5,%6,%7},{%8,%9},{%0,%1,%2,%3};" \
                 : "+f"((d)[0]), "+f"((d)[1]), "+f"((d)[2]), "+f"((d)[3]) \
                 : "r"((a)[0]), "r"((a)[1]), "r"((a)[2]), "r"((a)[3]), \
                   "r"((b)[0]), "r"((b)[1]))

__device__ __forceinline__ void split3(float v, bf16& h, bf16& m, bf16& l) {
    h = __float2bfloat16(v);
    float r1 = v - __bfloat162float(h);
    m = __float2bfloat16(r1);
    l = __float2bfloat16(r1 - __bfloat162float(m));
}
__device__ __forceinline__ int korig_add(int k) {
    return (k < 512) ? 0 : (k < 1408 ? 1024 : 2048);
}

// ---------- preprocessing ----------
__global__ void prep_w_kernel(const float* __restrict__ w_rec, const float* __restrict__ mask) {
    __shared__ float tile[32][33];
    int k0 = blockIdx.x * 32, n0 = blockIdx.y * 32;
    int orig0 = k0 + korig_add(k0);
    #pragma unroll
    for (int i = 0; i < 4; i++) {
        int r = threadIdx.y + i * 8;
        size_t s = (size_t)(orig0 + r) * N_TOT + n0 + threadIdx.x;
        tile[r][threadIdx.x] = fabsf(w_rec[s]) * mask[s];
    }
    __syncthreads();
    #pragma unroll
    for (int i = 0; i < 4; i++) {
        int rr = threadIdx.y + i * 8;
        float v = tile[threadIdx.x][rr];
        bf16 h, m, l;
        split3(v, h, m, l);
        size_t d = (size_t)(n0 + rr) * K_CMP + k0 + threadIdx.x;
        g_WtHi[d] = h; g_WtMi[d] = m; g_WtLo[d] = l;
    }
}
__global__ void prep_win_kernel(const float* __restrict__ w_in) {
    size_t i = (size_t)blockIdx.x * blockDim.x + threadIdx.x;
    if (i >= (size_t)N_IN * N_TOT) return;
    int kin = (int)(i / N_TOT), n = (int)(i - (size_t)kin * N_TOT);
    bf16 h, m, l;
    split3(w_in[i], h, m, l);
    size_t d = (size_t)n * N_IN + kin;
    g_WinHi[d] = h; g_WinMi[d] = m; g_WinLo[d] = l;
}
__global__ void prep_x_kernel(const float* __restrict__ x) {
    size_t i = (size_t)blockIdx.x * blockDim.x + threadIdx.x;
    if (i >= (size_t)T_STEPS * BATCH * N_IN) return;
    bf16 h, m, l;
    split3(x[i], h, m, l);
    g_xHi[i] = h; g_xMi[i] = m; g_xLo[i] = l;
}
__global__ void init_state_kernel(const float* __restrict__ h0) {
    size_t i = (size_t)blockIdx.x * blockDim.x + threadIdx.x;
    if (i >= (size_t)BATCH * N_TOT) return;
    int n = (int)(i % N_TOT), b = (int)(i / N_TOT);
    float hv = h0[i];
    g_h[i] = hv;
    int g = n / REGION, m = n - g * REGION;
    if (m >= 512 && m < 1536) {
        g_rd[0][(size_t)b * 2048 + g * 1024 + (m - 512)] = tanhf(hv);
    } else {
        float r = fmaxf(hv, 0.f);
        int k = g * 896 + (m < 512 ? m : 512 + (m - 1536));
        bf16 hh, mm, ll;
        split3(r, hh, mm, ll);
        size_t d = (size_t)b * K_CMP + k;
        g_rHi[0][d] = hh; g_rMi[0][d] = mm; g_rLo[0][d] = ll;
    }
}
__global__ void reset_barrier_kernel() { g_bar_count = 0u; g_bar_gen = 0u; }

__device__ __forceinline__ void grid_barrier(unsigned gen) {
    __syncthreads();
    if (threadIdx.x == 0) {
        __threadfence();
        if (atomicAdd(&g_bar_count, 1u) == NBLK - 1u) {
            g_bar_count = 0u;
            __threadfence();
            asm volatile("st.release.gpu.u32 [%0], %1;" :: "l"(&g_bar_gen), "r"(gen + 1u) : "memory");
        } else {
            unsigned cur;
            do {
                __nanosleep(64);
                asm volatile("ld.acquire.gpu.u32 %0, [%1];" : "=r"(cur) : "l"(&g_bar_gen) : "memory");
            } while (cur == gen);
        }
    }
    __syncthreads();
}

// one K64 chunk into stage stg: A 64x128B (hi,mi,lo) + B 64x128B (hi,mi,lo)
__device__ __forceinline__ void load_chunk(uint32_t sb, int stg, int c, int t,
                                           int mt, int b0, int pr, int tid) {
    uint32_t st = sb + stg * STAGE_BYTES;
    int row = tid >> 1, s0 = (tid & 1) * 4;
    const bf16 *Ah, *Am, *Al, *Bh, *Bm, *Bl;
    if (c < CH_TOT - 1) {
        size_t ao = (size_t)(mt * 64 + row) * K_CMP + c * 64;
        Ah = g_WtHi + ao; Am = g_WtMi + ao; Al = g_WtLo + ao;
        size_t bo = (size_t)(b0 + row) * K_CMP + c * 64;
        Bh = g_rHi[pr] + bo; Bm = g_rMi[pr] + bo; Bl = g_rLo[pr] + bo;
    } else {
        size_t ao = (size_t)(mt * 64 + row) * N_IN;
        Ah = g_WinHi + ao; Am = g_WinMi + ao; Al = g_WinLo + ao;
        size_t bo = ((size_t)t * BATCH + b0 + row) * N_IN;
        Bh = g_xHi + bo; Bm = g_xMi + bo; Bl = g_xLo + bo;
    }
    #pragma unroll
    for (int i = 0; i < 4; i++) {
        int s = s0 + i;
        uint32_t d = SWZ((uint32_t)(row * 128 + s * 16));
        cp16(st + A_HI + d, Ah + s * 8);
        cp16(st + A_MI + d, Am + s * 8);
        cp16(st + A_LO + d, Al + s * 8);
        cp16(st + B_HI + d, Bh + s * 8);
        cp16(st + B_MI + d, Bm + s * 8);
        cp16(st + B_LO + d, Bl + s * 8);
    }
    asm volatile("cp.async.commit_group;" ::: "memory");
}

__global__ void __launch_bounds__(128, 1)
rollout_kernel(const float* __restrict__ noise, const float* __restrict__ bias,
               const float* __restrict__ w_out, float* __restrict__ out) {
    extern __shared__ __align__(1024) char sm[];
    uint32_t sb = smem_u32(sm);
    const int tid = threadIdx.x, bx = blockIdx.x;
    unsigned gen = 0;

    if (bx < NB_GEMM) {
        const int mt = bx >> 1, b0 = (bx & 1) * 64;
        const int n0t = mt * 64;
        const int g = n0t / REGION, m0 = n0t - g * REGION;
        const bool isES = (m0 < 512), isDend = (m0 >= 512 && m0 < 1536);
        float* dsm = (float*)(sm + DSM_OFF);
        float* bias_s = (float*)(sm + BIAS_OFF);

        const int wid = tid >> 5, lane = tid & 31;
        const int mw = (wid >> 1) * 32, nw = (wid & 1) * 32;
        const int g8 = lane >> 3, r8 = lane & 7;
        const int aRow = mw + (g8 & 1) * 8 + r8;
        const uint32_t aKh = (uint32_t)((g8 >> 1) * 16);
        const uint32_t aXor = (uint32_t)((aRow & 7) * 16);
        const uint32_t aB0 = (uint32_t)(aRow * 128);
        const int bRow = nw + (g8 >> 1) * 8 + r8;
        const uint32_t bKh = (uint32_t)((g8 & 1) * 16);
        const uint32_t bXor = (uint32_t)((bRow & 7) * 16);
        const uint32_t bB0 = (uint32_t)(bRow * 128);

        if (tid < 64) bias_s[tid] = bias[n0t + tid];
        __syncthreads();

        for (int t = 0; t < T_STEPS; t++) {
            const int pr = t & 1, pw = 1 - pr;
            float acc[2][4][4];   // Kahan running sum
            float cmp[2][4][4];   // Kahan compensation
            #pragma unroll
            for (int a = 0; a < 2; a++)
                #pragma unroll
                for (int c = 0; c < 4; c++)
                    #pragma unroll
                    for (int d = 0; d < 4; d++) { acc[a][c][d] = 0.f; cmp[a][c][d] = 0.f; }

            load_chunk(sb, 0, 0, t, mt, b0, pr, tid);
            load_chunk(sb, 1, 1, t, mt, b0, pr, tid);
            #pragma unroll 1
            for (int c = 0; c < CH_TOT; c++) {
                if (c + 2 < CH_TOT) {
                    load_chunk(sb, (c + 2) % 3, c + 2, t, mt, b0, pr, tid);
                    asm volatile("cp.async.wait_group 2;" ::: "memory");
                } else if (c + 1 < CH_TOT) {
                    asm volatile("cp.async.wait_group 1;" ::: "memory");
                } else {
                    asm volatile("cp.async.wait_group 0;" ::: "memory");
                }
                __syncthreads();
                uint32_t st = sb + (uint32_t)(c % 3) * STAGE_BYTES;

                // fresh chunk accumulator: keeps per-MMA rounding at chunk scale
                float sub[2][4][4];
                #pragma unroll
                for (int a = 0; a < 2; a++)
                    #pragma unroll
                    for (int cc = 0; cc < 4; cc++)
                        #pragma unroll
                        for (int d = 0; d < 4; d++) sub[a][cc][d] = 0.f;

                #pragma unroll
                for (int ks = 0; ks < 4; ks++) {
                    const uint32_t ka = ((uint32_t)(ks * 32) + aKh) ^ aXor;
                    const uint32_t kb = ((uint32_t)(ks * 32) + bKh) ^ bXor;
                    uint32_t ah[2][4], am[2][4], al[2][4];
                    uint32_t bh[2][4], bm[2][4], bl[2][4];
                    #pragma unroll
                    for (int mb = 0; mb < 2; mb++) {
                        uint32_t ra = st + aB0 + (uint32_t)(mb * 16 * 128) + ka;
                        LDSM4(ah[mb][0], ah[mb][1], ah[mb][2], ah[mb][3], ra + A_HI);
                        LDSM4(am[mb][0], am[mb][1], am[mb][2], am[mb][3], ra + A_MI);
                        LDSM4(al[mb][0], al[mb][1], al[mb][2], al[mb][3], ra + A_LO);
                    }
                    #pragma unroll
                    for (int nb = 0; nb < 2; nb++) {
                        uint32_t rb = st + bB0 + (uint32_t)(nb * 16 * 128) + kb;
                        LDSM4(bh[nb][0], bh[nb][1], bh[nb][2], bh[nb][3], rb + B_HI);
                        LDSM4(bm[nb][0], bm[nb][1], bm[nb][2], bm[nb][3], rb + B_MI);
                        LDSM4(bl[nb][0], bl[nb][1], bl[nb][2], bl[nb][3], rb + B_LO);
                    }
                    #pragma unroll
                    for (int mb = 0; mb < 2; mb++)
                        #pragma unroll
                        for (int nb = 0; nb < 2; nb++)
                            #pragma unroll
                            for (int h = 0; h < 2; h++) {
                                float* d = sub[mb][nb * 2 + h];
                                MMA(d, ah[mb], &bh[nb][h * 2]);   // hh
                                MMA(d, ah[mb], &bm[nb][h * 2]);   // hm
                                MMA(d, am[mb], &bh[nb][h * 2]);   // mh
                                MMA(d, ah[mb], &bl[nb][h * 2]);   // hl
                                MMA(d, am[mb], &bm[nb][h * 2]);   // mm
                                MMA(d, al[mb], &bh[nb][h * 2]);   // lh
                            }
                }

                // Kahan-fold chunk accumulator into running total
                #pragma unroll
                for (int a = 0; a < 2; a++)
                    #pragma unroll
                    for (int cc = 0; cc < 4; cc++)
                        #pragma unroll
                        for (int d = 0; d < 4; d++) {
                            float y = sub[a][cc][d] - cmp[a][cc][d];
                            float tt = acc[a][cc][d] + y;
                            cmp[a][cc][d] = (tt - acc[a][cc][d]) - y;
                            acc[a][cc][d] = tt;
                        }
                __syncthreads();
            }

            // fragments -> dsm[n][b] (stride 72)
            {
                const int mr = lane >> 2, bc = (lane & 3) * 2;
                #pragma unroll
                for (int mb = 0; mb < 2; mb++)
                    #pragma unroll
                    for (int nf = 0; nf < 4; nf++) {
                        int m = mw + mb * 16 + mr;
                        int bcol = nw + nf * 8 + bc;
                        *(float2*)&dsm[m * 72 + bcol] =
                            make_float2(acc[mb][nf][0], acc[mb][nf][1]);
                        *(float2*)&dsm[(m + 8) * 72 + bcol] =
                            make_float2(acc[mb][nf][2], acc[mb][nf][3]);
                    }
            }
            __syncthreads();

            // ---- epilogue: batch-major state update ----
            {
                const int bl2 = tid & 63, hf = tid >> 6;
                const int b = b0 + bl2, nl0 = hf * 32;
                float* __restrict__ hp = g_h + (size_t)b * N_TOT + n0t + nl0;
                const float* __restrict__ nz =
                    noise + ((size_t)t * BATCH + b) * N_TOT + n0t + nl0;
                const float* __restrict__ d0 = isES ?
                    g_rd[pr] + (size_t)b * 2048 + g * 1024 + (m0 + nl0) : nullptr;
                const float* __restrict__ d1 = isES ? d0 + 512 : nullptr;
                float* __restrict__ rdw = isDend ?
                    g_rd[pw] + (size_t)b * 2048 + g * 1024 + (m0 - 512) + nl0 : nullptr;
                const int k0 = g * 896 + (m0 < 512 ? m0 : 512 + (m0 - 1536)) + nl0;
                bf16* __restrict__ rhw = g_rHi[pw] + (size_t)b * K_CMP + k0;
                bf16* __restrict__ rmw = g_rMi[pw] + (size_t)b * K_CMP + k0;
                bf16* __restrict__ rlw = g_rLo[pw] + (size_t)b * K_CMP + k0;
                #pragma unroll 4
                for (int i = 0; i < 32; i += 4) {
                    float4 hv = *(const float4*)&hp[i];
                    float4 nv = *(const float4*)&nz[i];
                    float tv[4], hn[4];
                    #pragma unroll
                    for (int j = 0; j < 4; j++)
                        tv[j] = dsm[(nl0 + i + j) * 72 + bl2] + bias_s[nl0 + i + j];
                    if (isES) {
                        float4 a0 = *(const float4*)&d0[i];
                        float4 a1 = *(const float4*)&d1[i];
                        tv[0] += a0.x + a1.x; tv[1] += a0.y + a1.y;
                        tv[2] += a0.z + a1.z; tv[3] += a0.w + a1.w;
                    }
                    hn[0] = 0.8f * hv.x + DECAY * tv[0] + NOISE_SCALE * nv.x;
                    hn[1] = 0.8f * hv.y + DECAY * tv[1] + NOISE_SCALE * nv.y;
                    hn[2] = 0.8f * hv.z + DECAY * tv[2] + NOISE_SCALE * nv.z;
                    hn[3] = 0.8f * hv.w + DECAY * tv[3] + NOISE_SCALE * nv.w;
                    *(float4*)&hp[i] = make_float4(hn[0], hn[1], hn[2], hn[3]);
                    if (isDend) {
                        *(float4*)&rdw[i] = make_float4(tanhf(hn[0]), tanhf(hn[1]),
                                                        tanhf(hn[2]), tanhf(hn[3]));
                    } else {
                        uint32_t hw[2], mw2[2], lw[2];
                        #pragma unroll
                        for (int p = 0; p < 2; p++) {
                            float r0 = fmaxf(hn[p * 2], 0.f), r1 = fmaxf(hn[p * 2 + 1], 0.f);
                            bf16 h0b, m0b, l0b, h1b, m1b, l1b;
                            split3(r0, h0b, m0b, l0b);
                            split3(r1, h1b, m1b, l1b);
                            hw[p] = (uint32_t)__bfloat16_as_ushort(h0b) |
                                    ((uint32_t)__bfloat16_as_ushort(h1b) << 16);
                            mw2[p] = (uint32_t)__bfloat16_as_ushort(m0b) |
                                     ((uint32_t)__bfloat16_as_ushort(m1b) << 16);
                            lw[p] = (uint32_t)__bfloat16_as_ushort(l0b) |
                                    ((uint32_t)__bfloat16_as_ushort(l1b) << 16);
                        }
                        *(uint2*)&rhw[i] = make_uint2(hw[0], hw[1]);
                        *(uint2*)&rmw[i] = make_uint2(mw2[0], mw2[1]);
                        *(uint2*)&rlw[i] = make_uint2(lw[0], lw[1]);
                    }
                }
            }
            grid_barrier(gen); gen++;
        }
    } else {
        const int o = bx - NB_GEMM;
        float* wcol = (float*)sm;
        for (int s = tid; s < N_ES; s += 128) wcol[s] = w_out[(size_t)s * N_OUT + o];
        __syncthreads();
        for (int t = 0; t <= T_STEPS; t++) {
            if (t > 0) {
                const int tt = t - 1, buf = (tt + 1) & 1;
                const bf16* __restrict__ rh = g_rHi[buf] + (size_t)tid * K_CMP;
                const bf16* __restrict__ rm = g_rMi[buf] + (size_t)tid * K_CMP;
                const bf16* __restrict__ rl = g_rLo[buf] + (size_t)tid * K_CMP;
                float acc = 0.f;
                #pragma unroll 8
                for (int s = 0; s < N_ES; s++)
                    acc += (__bfloat162float(rh[s]) + __bfloat162float(rm[s])
                            + __bfloat162float(rl[s])) * wcol[s];
                out[((size_t)tt * BATCH + tid) * N_OUT + o] = acc;
            }
            if (t < T_STEPS) { grid_barrier(gen); gen++; }
        }
    }
}

extern "C" void kernel_launch(void* const* d_in, const int* in_sizes, int n_in,
                              void* d_out, int out_size) {
    const float* x     = (const float*)d_in[0];
    const float* noise = (const float*)d_in[1];
    const float* w_rec = (const float*)d_in[2];
    const float* w_in  = (const float*)d_in[3];
    const float* w_out = (const float*)d_in[4];
    const float* bias  = (const float*)d_in[5];
    const float* h0    = (const float*)d_in[6];
    const float* mask  = (const float*)d_in[7];
    float* out = (float*)d_out;
    (void)in_sizes; (void)n_in; (void)out_size;

    cudaFuncSetAttribute(rollout_kernel, cudaFuncAttributeMaxDynamicSharedMemorySize, SMEM_DYN);

    { dim3 g(K_CMP / 32, N_TOT / 32); prep_w_kernel<<<g, dim3(32, 8)>>>(w_rec, mask); }
    { size_t n = (size_t)N_IN * N_TOT; prep_win_kernel<<<(int)((n + 255) / 256), 256>>>(w_in); }
    { size_t n = (size_t)T_STEPS * BATCH * N_IN; prep_x_kernel<<<(int)((n + 255) / 256), 256>>>(x); }
    { size_t n = (size_t)BATCH * N_TOT; init_state_kernel<<<(int)((n + 255) / 256), 256>>>(h0); }
    reset_barrier_kernel<<<1, 1>>>();

    rollout_kernel<<<NBLK, 128, SMEM_DYN>>>(noise, bias, w_out, out);
}

// round 14
// speedup vs baseline: 2.0351x; 1.1405x over previous
#include <cuda_runtime.h>
#include <cuda_bf16.h>
#include <cstdint>
#include <cstddef>

#define T_STEPS 200
#define BATCH 128
#define N_IN 64
#define N_OUT 10
#define N_ES 512
#define REGION 1920
#define N_TOT 3840
#define K_CMP 1792
#define NB_GEMM 120
#define NBLK 130
#define NTHR 256
#define CH_TOT 29            /* 28 recurrent K64 chunks + 1 input chunk */
#define DECAY 0.2f
#define NOISE_SCALE 0.0063245553203367585f

#define STAGE_BYTES 49152
#define A_HI 0
#define A_MI 8192
#define A_LO 16384
#define B_HI 24576
#define B_MI 32768
#define B_LO 40960
#define DSM_OFF 147456       /* 64 x 72 floats = 18432 B */
#define BIAS_OFF 165888
#define SMEM_DYN 166400

typedef unsigned long long u64;
typedef __nv_bfloat16 bf16;

__device__ __align__(16) bf16  g_WtHi[(size_t)N_TOT * K_CMP];
__device__ __align__(16) bf16  g_WtMi[(size_t)N_TOT * K_CMP];
__device__ __align__(16) bf16  g_WtLo[(size_t)N_TOT * K_CMP];
__device__ __align__(16) bf16  g_WinHi[(size_t)N_TOT * N_IN];
__device__ __align__(16) bf16  g_WinMi[(size_t)N_TOT * N_IN];
__device__ __align__(16) bf16  g_WinLo[(size_t)N_TOT * N_IN];
__device__ __align__(16) bf16  g_xHi[(size_t)T_STEPS * BATCH * N_IN];
__device__ __align__(16) bf16  g_xMi[(size_t)T_STEPS * BATCH * N_IN];
__device__ __align__(16) bf16  g_xLo[(size_t)T_STEPS * BATCH * N_IN];
__device__ __align__(16) bf16  g_rHi[2][(size_t)BATCH * K_CMP];
__device__ __align__(16) bf16  g_rMi[2][(size_t)BATCH * K_CMP];
__device__ __align__(16) bf16  g_rLo[2][(size_t)BATCH * K_CMP];
__device__ __align__(16) float g_rd[2][(size_t)BATCH * 2048];
__device__ __align__(16) float g_h[(size_t)BATCH * N_TOT];
__device__ unsigned g_bar_count, g_bar_gen;

__device__ __forceinline__ uint32_t smem_u32(const void* p) {
    uint32_t a;
    asm("{ .reg .u64 t; cvta.to.shared.u64 t, %1; cvt.u32.u64 %0, t; }" : "=r"(a) : "l"(p));
    return a;
}
#define SWZ(o) ((o) ^ (((o) >> 3) & 0x70))
__device__ __forceinline__ void cp16(uint32_t d, const void* s) {
    asm volatile("cp.async.cg.shared.global [%0], [%1], 16;" :: "r"(d), "l"(s));
}
#define LDSM4(r0, r1, r2, r3, a) \
    asm volatile("ldmatrix.sync.aligned.m8n8.x4.shared.b16 {%0,%1,%2,%3}, [%4];" \
                 : "=r"(r0), "=r"(r1), "=r"(r2), "=r"(r3) : "r"(a))
#define MMA(d, a, b) \
    asm volatile("mma.sync.aligned.m16n8k16.row.col.f32.bf16.bf16.f32 " \
                 "{%0,%1,%2,%3},{%4,%5,%6,%7},{%8,%9},{%0,%1,%2,%3};" \
                 : "+f"((d)[0]), "+f"((d)[1]), "+f"((d)[2]), "+f"((d)[3]) \
                 : "r"((a)[0]), "r"((a)[1]), "r"((a)[2]), "r"((a)[3]), \
                   "r"((b)[0]), "r"((b)[1]))

__device__ __forceinline__ void split3(float v, bf16& h, bf16& m, bf16& l) {
    h = __float2bfloat16(v);
    float r1 = v - __bfloat162float(h);
    m = __float2bfloat16(r1);
    l = __float2bfloat16(r1 - __bfloat162float(m));
}
__device__ __forceinline__ int korig_add(int k) {
    return (k < 512) ? 0 : (k < 1408 ? 1024 : 2048);
}

// ---------- preprocessing ----------
__global__ void prep_w_kernel(const float* __restrict__ w_rec, const float* __restrict__ mask) {
    __shared__ float tile[32][33];
    int k0 = blockIdx.x * 32, n0 = blockIdx.y * 32;
    int orig0 = k0 + korig_add(k0);
    #pragma unroll
    for (int i = 0; i < 4; i++) {
        int r = threadIdx.y + i * 8;
        size_t s = (size_t)(orig0 + r) * N_TOT + n0 + threadIdx.x;
        tile[r][threadIdx.x] = fabsf(w_rec[s]) * mask[s];
    }
    __syncthreads();
    #pragma unroll
    for (int i = 0; i < 4; i++) {
        int rr = threadIdx.y + i * 8;
        float v = tile[threadIdx.x][rr];
        bf16 h, m, l;
        split3(v, h, m, l);
        size_t d = (size_t)(n0 + rr) * K_CMP + k0 + threadIdx.x;
        g_WtHi[d] = h; g_WtMi[d] = m; g_WtLo[d] = l;
    }
}
__global__ void prep_win_kernel(const float* __restrict__ w_in) {
    size_t i = (size_t)blockIdx.x * blockDim.x + threadIdx.x;
    if (i >= (size_t)N_IN * N_TOT) return;
    int kin = (int)(i / N_TOT), n = (int)(i - (size_t)kin * N_TOT);
    bf16 h, m, l;
    split3(w_in[i], h, m, l);
    size_t d = (size_t)n * N_IN + kin;
    g_WinHi[d] = h; g_WinMi[d] = m; g_WinLo[d] = l;
}
__global__ void prep_x_kernel(const float* __restrict__ x) {
    size_t i = (size_t)blockIdx.x * blockDim.x + threadIdx.x;
    if (i >= (size_t)T_STEPS * BATCH * N_IN) return;
    bf16 h, m, l;
    split3(x[i], h, m, l);
    g_xHi[i] = h; g_xMi[i] = m; g_xLo[i] = l;
}
__global__ void init_state_kernel(const float* __restrict__ h0) {
    size_t i = (size_t)blockIdx.x * blockDim.x + threadIdx.x;
    if (i >= (size_t)BATCH * N_TOT) return;
    int n = (int)(i % N_TOT), b = (int)(i / N_TOT);
    float hv = h0[i];
    g_h[i] = hv;
    int g = n / REGION, m = n - g * REGION;
    if (m >= 512 && m < 1536) {
        g_rd[0][(size_t)b * 2048 + g * 1024 + (m - 512)] = tanhf(hv);
    } else {
        float r = fmaxf(hv, 0.f);
        int k = g * 896 + (m < 512 ? m : 512 + (m - 1536));
        bf16 hh, mm, ll;
        split3(r, hh, mm, ll);
        size_t d = (size_t)b * K_CMP + k;
        g_rHi[0][d] = hh; g_rMi[0][d] = mm; g_rLo[0][d] = ll;
    }
}
__global__ void reset_barrier_kernel() { g_bar_count = 0u; g_bar_gen = 0u; }

__device__ __forceinline__ void grid_barrier(unsigned gen) {
    __syncthreads();
    if (threadIdx.x == 0) {
        __threadfence();
        if (atomicAdd(&g_bar_count, 1u) == NBLK - 1u) {
            g_bar_count = 0u;
            __threadfence();
            asm volatile("st.release.gpu.u32 [%0], %1;" :: "l"(&g_bar_gen), "r"(gen + 1u) : "memory");
        } else {
            unsigned cur;
            do {
                __nanosleep(64);
                asm volatile("ld.acquire.gpu.u32 %0, [%1];" : "=r"(cur) : "l"(&g_bar_gen) : "memory");
            } while (cur == gen);
        }
    }
    __syncthreads();
}

// one K64 chunk into stage stg (256 threads): 6 streams x 64 rows x 128B
__device__ __forceinline__ void load_chunk(uint32_t sb, int stg, int c, int t,
                                           int mt, int b0, int pr, int tid) {
    uint32_t st = sb + stg * STAGE_BYTES;
    int row = tid >> 2, s0 = (tid & 3) * 2;
    const bf16 *Ah, *Am, *Al, *Bh, *Bm, *Bl;
    if (c < CH_TOT - 1) {
        size_t ao = (size_t)(mt * 64 + row) * K_CMP + c * 64;
        Ah = g_WtHi + ao; Am = g_WtMi + ao; Al = g_WtLo + ao;
        size_t bo = (size_t)(b0 + row) * K_CMP + c * 64;
        Bh = g_rHi[pr] + bo; Bm = g_rMi[pr] + bo; Bl = g_rLo[pr] + bo;
    } else {
        size_t ao = (size_t)(mt * 64 + row) * N_IN;
        Ah = g_WinHi + ao; Am = g_WinMi + ao; Al = g_WinLo + ao;
        size_t bo = ((size_t)t * BATCH + b0 + row) * N_IN;
        Bh = g_xHi + bo; Bm = g_xMi + bo; Bl = g_xLo + bo;
    }
    #pragma unroll
    for (int i = 0; i < 2; i++) {
        int s = s0 + i;
        uint32_t d = SWZ((uint32_t)(row * 128 + s * 16));
        cp16(st + A_HI + d, Ah + s * 8);
        cp16(st + A_MI + d, Am + s * 8);
        cp16(st + A_LO + d, Al + s * 8);
        cp16(st + B_HI + d, Bh + s * 8);
        cp16(st + B_MI + d, Bm + s * 8);
        cp16(st + B_LO + d, Bl + s * 8);
    }
    asm volatile("cp.async.commit_group;" ::: "memory");
}

__global__ void __launch_bounds__(NTHR, 1)
rollout_kernel(const float* __restrict__ noise, const float* __restrict__ bias,
               const float* __restrict__ w_out, float* __restrict__ out) {
    extern __shared__ __align__(1024) char sm[];
    uint32_t sb = smem_u32(sm);
    const int tid = threadIdx.x, bx = blockIdx.x;
    unsigned gen = 0;

    if (bx < NB_GEMM) {
        const int mt = bx >> 1, b0 = (bx & 1) * 64;
        const int n0t = mt * 64;
        const int g = n0t / REGION, m0 = n0t - g * REGION;
        const bool isES = (m0 < 512), isDend = (m0 >= 512 && m0 < 1536);
        float* dsm = (float*)(sm + DSM_OFF);
        float* bias_s = (float*)(sm + BIAS_OFF);

        const int wid = tid >> 5, lane = tid & 31;
        const int mw = (wid & 3) * 16, nw = (wid >> 2) * 32;
        const int g8 = lane >> 3, r8 = lane & 7;
        // A: one m16k16 row-major frag per warp
        const int aRow = mw + (g8 & 1) * 8 + r8;
        const uint32_t aKh = (uint32_t)((g8 >> 1) * 16);
        const uint32_t aXor = (uint32_t)((aRow & 7) * 16);
        const uint32_t aB0 = (uint32_t)(aRow * 128);
        // B: two n16 blocks ([n][k] rows)
        const uint32_t bKh = (uint32_t)((g8 & 1) * 16);
        uint32_t bB0[2], bXor[2];
        #pragma unroll
        for (int nb = 0; nb < 2; nb++) {
            int bRow = nw + nb * 16 + (g8 >> 1) * 8 + r8;
            bXor[nb] = (uint32_t)((bRow & 7) * 16);
            bB0[nb] = (uint32_t)(bRow * 128);
        }

        if (tid < 64) bias_s[tid] = bias[n0t + tid];
        __syncthreads();

        for (int t = 0; t < T_STEPS; t++) {
            const int pr = t & 1, pw = 1 - pr;
            float acc[4][4], cmp[4][4];
            #pragma unroll
            for (int c = 0; c < 4; c++)
                #pragma unroll
                for (int d = 0; d < 4; d++) { acc[c][d] = 0.f; cmp[c][d] = 0.f; }

            load_chunk(sb, 0, 0, t, mt, b0, pr, tid);
            load_chunk(sb, 1, 1, t, mt, b0, pr, tid);
            #pragma unroll 1
            for (int c = 0; c < CH_TOT; c++) {
                if (c + 2 < CH_TOT) {
                    load_chunk(sb, (c + 2) % 3, c + 2, t, mt, b0, pr, tid);
                    asm volatile("cp.async.wait_group 2;" ::: "memory");
                } else if (c + 1 < CH_TOT) {
                    asm volatile("cp.async.wait_group 1;" ::: "memory");
                } else {
                    asm volatile("cp.async.wait_group 0;" ::: "memory");
                }
                __syncthreads();
                uint32_t st = sb + (uint32_t)(c % 3) * STAGE_BYTES;

                // fresh chunk accumulator (keeps per-MMA rounding at chunk scale)
                float sub[4][4];
                #pragma unroll
                for (int cc = 0; cc < 4; cc++)
                    #pragma unroll
                    for (int d = 0; d < 4; d++) sub[cc][d] = 0.f;

                #pragma unroll
                for (int ks = 0; ks < 4; ks++) {
                    const uint32_t ka = ((uint32_t)(ks * 32) + aKh) ^ aXor;
                    uint32_t ah[4], am[4], al[4];
                    uint32_t bh[2][4], bm[2][4], bl[2][4];
                    {
                        uint32_t ra = st + aB0 + ka;
                        LDSM4(ah[0], ah[1], ah[2], ah[3], ra + A_HI);
                        LDSM4(am[0], am[1], am[2], am[3], ra + A_MI);
                        LDSM4(al[0], al[1], al[2], al[3], ra + A_LO);
                    }
                    #pragma unroll
                    for (int nb = 0; nb < 2; nb++) {
                        uint32_t rb = st + bB0[nb] + (((uint32_t)(ks * 32) + bKh) ^ bXor[nb]);
                        LDSM4(bh[nb][0], bh[nb][1], bh[nb][2], bh[nb][3], rb + B_HI);
                        LDSM4(bm[nb][0], bm[nb][1], bm[nb][2], bm[nb][3], rb + B_MI);
                        LDSM4(bl[nb][0], bl[nb][1], bl[nb][2], bl[nb][3], rb + B_LO);
                    }
                    #pragma unroll
                    for (int nb = 0; nb < 2; nb++)
                        #pragma unroll
                        for (int h = 0; h < 2; h++) {
                            float* d = sub[nb * 2 + h];
                            MMA(d, ah, &bh[nb][h * 2]);   // hh
                            MMA(d, ah, &bm[nb][h * 2]);   // hm
                            MMA(d, am, &bh[nb][h * 2]);   // mh
                            MMA(d, ah, &bl[nb][h * 2]);   // hl
                            MMA(d, am, &bm[nb][h * 2]);   // mm
                            MMA(d, al, &bh[nb][h * 2]);   // lh
                        }
                }

                // Kahan-fold chunk accumulator into running total
                #pragma unroll
                for (int cc = 0; cc < 4; cc++)
                    #pragma unroll
                    for (int d = 0; d < 4; d++) {
                        float y = sub[cc][d] - cmp[cc][d];
                        float tt = acc[cc][d] + y;
                        cmp[cc][d] = (tt - acc[cc][d]) - y;
                        acc[cc][d] = tt;
                    }
                __syncthreads();
            }

            // fragments -> dsm[n][b] (stride 72)
            {
                const int mr = lane >> 2, bc = (lane & 3) * 2;
                #pragma unroll
                for (int nf = 0; nf < 4; nf++) {
                    int m = mw + mr;
                    int bcol = nw + nf * 8 + bc;
                    *(float2*)&dsm[m * 72 + bcol] = make_float2(acc[nf][0], acc[nf][1]);
                    *(float2*)&dsm[(m + 8) * 72 + bcol] = make_float2(acc[nf][2], acc[nf][3]);
                }
            }
            __syncthreads();

            // ---- epilogue: batch-major state update (4 quadrants of 16 n) ----
            {
                const int bl2 = tid & 63, q = tid >> 6;
                const int b = b0 + bl2, nl0 = q * 16;
                float* __restrict__ hp = g_h + (size_t)b * N_TOT + n0t + nl0;
                const float* __restrict__ nz =
                    noise + ((size_t)t * BATCH + b) * N_TOT + n0t + nl0;
                const float* __restrict__ d0 = isES ?
                    g_rd[pr] + (size_t)b * 2048 + g * 1024 + (m0 + nl0) : nullptr;
                const float* __restrict__ d1 = isES ? d0 + 512 : nullptr;
                float* __restrict__ rdw = isDend ?
                    g_rd[pw] + (size_t)b * 2048 + g * 1024 + (m0 - 512) + nl0 : nullptr;
                const int k0 = g * 896 + (m0 < 512 ? m0 : 512 + (m0 - 1536)) + nl0;
                bf16* __restrict__ rhw = g_rHi[pw] + (size_t)b * K_CMP + k0;
                bf16* __restrict__ rmw = g_rMi[pw] + (size_t)b * K_CMP + k0;
                bf16* __restrict__ rlw = g_rLo[pw] + (size_t)b * K_CMP + k0;
                #pragma unroll
                for (int i = 0; i < 16; i += 4) {
                    float4 hv = *(const float4*)&hp[i];
                    float4 nv = *(const float4*)&nz[i];
                    float tv[4], hn[4];
                    #pragma unroll
                    for (int j = 0; j < 4; j++)
                        tv[j] = dsm[(nl0 + i + j) * 72 + bl2] + bias_s[nl0 + i + j];
                    if (isES) {
                        float4 a0 = *(const float4*)&d0[i];
                        float4 a1 = *(const float4*)&d1[i];
                        tv[0] += a0.x + a1.x; tv[1] += a0.y + a1.y;
                        tv[2] += a0.z + a1.z; tv[3] += a0.w + a1.w;
                    }
                    hn[0] = 0.8f * hv.x + DECAY * tv[0] + NOISE_SCALE * nv.x;
                    hn[1] = 0.8f * hv.y + DECAY * tv[1] + NOISE_SCALE * nv.y;
                    hn[2] = 0.8f * hv.z + DECAY * tv[2] + NOISE_SCALE * nv.z;
                    hn[3] = 0.8f * hv.w + DECAY * tv[3] + NOISE_SCALE * nv.w;
                    *(float4*)&hp[i] = make_float4(hn[0], hn[1], hn[2], hn[3]);
                    if (isDend) {
                        *(float4*)&rdw[i] = make_float4(tanhf(hn[0]), tanhf(hn[1]),
                                                        tanhf(hn[2]), tanhf(hn[3]));
                    } else {
                        uint32_t hw[2], mw2[2], lw[2];
                        #pragma unroll
                        for (int p = 0; p < 2; p++) {
                            float r0 = fmaxf(hn[p * 2], 0.f), r1 = fmaxf(hn[p * 2 + 1], 0.f);
                            bf16 h0b, m0b, l0b, h1b, m1b, l1b;
                            split3(r0, h0b, m0b, l0b);
                            split3(r1, h1b, m1b, l1b);
                            hw[p] = (uint32_t)__bfloat16_as_ushort(h0b) |
                                    ((uint32_t)__bfloat16_as_ushort(h1b) << 16);
                            mw2[p] = (uint32_t)__bfloat16_as_ushort(m0b) |
                                     ((uint32_t)__bfloat16_as_ushort(m1b) << 16);
                            lw[p] = (uint32_t)__bfloat16_as_ushort(l0b) |
                                    ((uint32_t)__bfloat16_as_ushort(l1b) << 16);
                        }
                        *(uint2*)&rhw[i] = make_uint2(hw[0], hw[1]);
                        *(uint2*)&rmw[i] = make_uint2(mw2[0], mw2[1]);
                        *(uint2*)&rlw[i] = make_uint2(lw[0], lw[1]);
                    }
                }
            }
            grid_barrier(gen); gen++;
        }
    } else {
        const int o = bx - NB_GEMM;
        float* wcol = (float*)sm;
        for (int s = tid; s < N_ES; s += NTHR) wcol[s] = w_out[(size_t)s * N_OUT + o];
        __syncthreads();
        for (int t = 0; t <= T_STEPS; t++) {
            if (t > 0 && tid < BATCH) {
                const int tt = t - 1, buf = (tt + 1) & 1;
                const bf16* __restrict__ rh = g_rHi[buf] + (size_t)tid * K_CMP;
                const bf16* __restrict__ rm = g_rMi[buf] + (size_t)tid * K_CMP;
                const bf16* __restrict__ rl = g_rLo[buf] + (size_t)tid * K_CMP;
                float acc = 0.f;
                #pragma unroll 8
                for (int s = 0; s < N_ES; s++)
                    acc += (__bfloat162float(rh[s]) + __bfloat162float(rm[s])
                            + __bfloat162float(rl[s])) * wcol[s];
                out[((size_t)tt * BATCH + tid) * N_OUT + o] = acc;
            }
            if (t < T_STEPS) { grid_barrier(gen); gen++; }
        }
    }
}

extern "C" void kernel_launch(void* const* d_in, const int* in_sizes, int n_in,
                              void* d_out, int out_size) {
    const float* x     = (const float*)d_in[0];
    const float* noise = (const float*)d_in[1];
    const float* w_rec = (const float*)d_in[2];
    const float* w_in  = (const float*)d_in[3];
    const float* w_out = (const float*)d_in[4];
    const float* bias  = (const float*)d_in[5];
    const float* h0    = (const float*)d_in[6];
    const float* mask  = (const float*)d_in[7];
    float* out = (float*)d_out;
    (void)in_sizes; (void)n_in; (void)out_size;

    cudaFuncSetAttribute(rollout_kernel, cudaFuncAttributeMaxDynamicSharedMemorySize, SMEM_DYN);

    { dim3 g(K_CMP / 32, N_TOT / 32); prep_w_kernel<<<g, dim3(32, 8)>>>(w_rec, mask); }
    { size_t n = (size_t)N_IN * N_TOT; prep_win_kernel<<<(int)((n + 255) / 256), 256>>>(w_in); }
    { size_t n = (size_t)T_STEPS * BATCH * N_IN; prep_x_kernel<<<(int)((n + 255) / 256), 256>>>(x); }
    { size_t n = (size_t)BATCH * N_TOT; init_state_kernel<<<(int)((n + 255) / 256), 256>>>(h0); }
    reset_barrier_kernel<<<1, 1>>>();

    rollout_kernel<<<NBLK, NTHR, SMEM_DYN>>>(noise, bias, w_out, out);
}

// round 15
// speedup vs baseline: 3.0779x; 1.5124x over previous
#include <cuda_runtime.h>
#include <cuda_bf16.h>
#include <cstdint>
#include <cstddef>

#define T_STEPS 200
#define BATCH 128
#define N_IN 64
#define N_OUT 10
#define N_ES 512
#define REGION 1920
#define N_TOT 3840
#define K_CMP 1792
#define NB_GEMM 120
#define NBLK 130
#define NTHR 256
#define CH_TOT 29            /* 28 recurrent K64 chunks + 1 input chunk */
#define DECAY 0.2f
#define NOISE_SCALE 0.0063245553203367585f

#define STAGE_BYTES 32768
#define A_HI 0
#define A_MI 8192
#define B_HI 16384
#define B_MI 24576
#define DSM_OFF 98304        /* 64 x 72 floats = 18432 B */
#define BIAS_OFF 116736
#define SMEM_DYN 117248

typedef unsigned long long u64;
typedef __nv_bfloat16 bf16;

__device__ __align__(16) bf16  g_WtHi[(size_t)N_TOT * K_CMP];
__device__ __align__(16) bf16  g_WtMi[(size_t)N_TOT * K_CMP];
__device__ __align__(16) bf16  g_WinHi[(size_t)N_TOT * N_IN];
__device__ __align__(16) bf16  g_WinMi[(size_t)N_TOT * N_IN];
__device__ __align__(16) bf16  g_xHi[(size_t)T_STEPS * BATCH * N_IN];
__device__ __align__(16) bf16  g_xMi[(size_t)T_STEPS * BATCH * N_IN];
__device__ __align__(16) bf16  g_rHi[2][(size_t)BATCH * K_CMP];
__device__ __align__(16) bf16  g_rMi[2][(size_t)BATCH * K_CMP];
__device__ __align__(16) float g_rd[2][(size_t)BATCH * 2048];
__device__ __align__(16) float g_h[(size_t)BATCH * N_TOT];
__device__ unsigned g_bar_count, g_bar_gen;

__device__ __forceinline__ uint32_t smem_u32(const void* p) {
    uint32_t a;
    asm("{ .reg .u64 t; cvta.to.shared.u64 t, %1; cvt.u32.u64 %0, t; }" : "=r"(a) : "l"(p));
    return a;
}
#define SWZ(o) ((o) ^ (((o) >> 3) & 0x70))
__device__ __forceinline__ void cp16(uint32_t d, const void* s) {
    asm volatile("cp.async.cg.shared.global [%0], [%1], 16;" :: "r"(d), "l"(s));
}
#define LDSM4(r0, r1, r2, r3, a) \
    asm volatile("ldmatrix.sync.aligned.m8n8.x4.shared.b16 {%0,%1,%2,%3}, [%4];" \
                 : "=r"(r0), "=r"(r1), "=r"(r2), "=r"(r3) : "r"(a))
#define MMA(d, a, b) \
    asm volatile("mma.sync.aligned.m16n8k16.row.col.f32.bf16.bf16.f32 " \
                 "{%0,%1,%2,%3},{%4,%5,%6,%7},{%8,%9},{%0,%1,%2,%3};" \
                 : "+f"((d)[0]), "+f"((d)[1]), "+f"((d)[2]), "+f"((d)[3]) \
                 : "r"((a)[0]), "r"((a)[1]), "r"((a)[2]), "r"((a)[3]), \
                   "r"((b)[0]), "r"((b)[1]))

__device__ __forceinline__ void split2(float v, bf16& h, bf16& m) {
    h = __float2bfloat16(v);
    m = __float2bfloat16(v - __bfloat162float(h));
}
__device__ __forceinline__ int korig_add(int k) {
    return (k < 512) ? 0 : (k < 1408 ? 1024 : 2048);
}

// ---------- preprocessing ----------
__global__ void prep_w_kernel(const float* __restrict__ w_rec, const float* __restrict__ mask) {
    __shared__ float tile[32][33];
    int k0 = blockIdx.x * 32, n0 = blockIdx.y * 32;
    int orig0 = k0 + korig_add(k0);
    #pragma unroll
    for (int i = 0; i < 4; i++) {
        int r = threadIdx.y + i * 8;
        size_t s = (size_t)(orig0 + r) * N_TOT + n0 + threadIdx.x;
        tile[r][threadIdx.x] = fabsf(w_rec[s]) * mask[s];
    }
    __syncthreads();
    #pragma unroll
    for (int i = 0; i < 4; i++) {
        int rr = threadIdx.y + i * 8;
        bf16 h, m;
        split2(tile[threadIdx.x][rr], h, m);
        size_t d = (size_t)(n0 + rr) * K_CMP + k0 + threadIdx.x;
        g_WtHi[d] = h; g_WtMi[d] = m;
    }
}
__global__ void prep_win_kernel(const float* __restrict__ w_in) {
    size_t i = (size_t)blockIdx.x * blockDim.x + threadIdx.x;
    if (i >= (size_t)N_IN * N_TOT) return;
    int kin = (int)(i / N_TOT), n = (int)(i - (size_t)kin * N_TOT);
    bf16 h, m;
    split2(w_in[i], h, m);
    size_t d = (size_t)n * N_IN + kin;
    g_WinHi[d] = h; g_WinMi[d] = m;
}
__global__ void prep_x_kernel(const float* __restrict__ x) {
    size_t i = (size_t)blockIdx.x * blockDim.x + threadIdx.x;
    if (i >= (size_t)T_STEPS * BATCH * N_IN) return;
    bf16 h, m;
    split2(x[i], h, m);
    g_xHi[i] = h; g_xMi[i] = m;
}
__global__ void init_state_kernel(const float* __restrict__ h0) {
    size_t i = (size_t)blockIdx.x * blockDim.x + threadIdx.x;
    if (i >= (size_t)BATCH * N_TOT) return;
    int n = (int)(i % N_TOT), b = (int)(i / N_TOT);
    float hv = h0[i];
    g_h[i] = hv;
    int g = n / REGION, m = n - g * REGION;
    if (m >= 512 && m < 1536) {
        g_rd[0][(size_t)b * 2048 + g * 1024 + (m - 512)] = tanhf(hv);
    } else {
        float r = fmaxf(hv, 0.f);
        int k = g * 896 + (m < 512 ? m : 512 + (m - 1536));
        bf16 hh, mm;
        split2(r, hh, mm);
        size_t d = (size_t)b * K_CMP + k;
        g_rHi[0][d] = hh; g_rMi[0][d] = mm;
    }
}
__global__ void reset_barrier_kernel() { g_bar_count = 0u; g_bar_gen = 0u; }

__device__ __forceinline__ void grid_barrier(unsigned gen) {
    __syncthreads();
    if (threadIdx.x == 0) {
        __threadfence();
        if (atomicAdd(&g_bar_count, 1u) == NBLK - 1u) {
            g_bar_count = 0u;
            __threadfence();
            asm volatile("st.release.gpu.u32 [%0], %1;" :: "l"(&g_bar_gen), "r"(gen + 1u) : "memory");
        } else {
            unsigned cur;
            do {
                __nanosleep(64);
                asm volatile("ld.acquire.gpu.u32 %0, [%1];" : "=r"(cur) : "l"(&g_bar_gen) : "memory");
            } while (cur == gen);
        }
    }
    __syncthreads();
}

// one K64 chunk into stage stg (256 threads): 4 streams x 64 rows x 128B
__device__ __forceinline__ void load_chunk(uint32_t sb, int stg, int c, int t,
                                           int mt, int b0, int pr, int tid) {
    uint32_t st = sb + stg * STAGE_BYTES;
    int row = tid >> 2, s0 = (tid & 3) * 2;
    const bf16 *Ah, *Am, *Bh, *Bm;
    if (c < CH_TOT - 1) {
        size_t ao = (size_t)(mt * 64 + row) * K_CMP + c * 64;
        Ah = g_WtHi + ao; Am = g_WtMi + ao;
        size_t bo = (size_t)(b0 + row) * K_CMP + c * 64;
        Bh = g_rHi[pr] + bo; Bm = g_rMi[pr] + bo;
    } else {
        size_t ao = (size_t)(mt * 64 + row) * N_IN;
        Ah = g_WinHi + ao; Am = g_WinMi + ao;
        size_t bo = ((size_t)t * BATCH + b0 + row) * N_IN;
        Bh = g_xHi + bo; Bm = g_xMi + bo;
    }
    #pragma unroll
    for (int i = 0; i < 2; i++) {
        int s = s0 + i;
        uint32_t d = SWZ((uint32_t)(row * 128 + s * 16));
        cp16(st + A_HI + d, Ah + s * 8);
        cp16(st + A_MI + d, Am + s * 8);
        cp16(st + B_HI + d, Bh + s * 8);
        cp16(st + B_MI + d, Bm + s * 8);
    }
    asm volatile("cp.async.commit_group;" ::: "memory");
}

__global__ void __launch_bounds__(NTHR, 1)
rollout_kernel(const float* __restrict__ noise, const float* __restrict__ bias,
               const float* __restrict__ w_out, float* __restrict__ out) {
    extern __shared__ __align__(1024) char sm[];
    uint32_t sb = smem_u32(sm);
    const int tid = threadIdx.x, bx = blockIdx.x;
    unsigned gen = 0;

    if (bx < NB_GEMM) {
        const int mt = bx >> 1, b0 = (bx & 1) * 64;
        const int n0t = mt * 64;
        const int g = n0t / REGION, m0 = n0t - g * REGION;
        const bool isES = (m0 < 512), isDend = (m0 >= 512 && m0 < 1536);
        float* dsm = (float*)(sm + DSM_OFF);
        float* bias_s = (float*)(sm + BIAS_OFF);

        const int wid = tid >> 5, lane = tid & 31;
        const int mw = (wid & 3) * 16, nw = (wid >> 2) * 32;
        const int g8 = lane >> 3, r8 = lane & 7;
        // A: one m16k16 row-major frag per warp
        const int aRow = mw + (g8 & 1) * 8 + r8;
        const uint32_t aKh = (uint32_t)((g8 >> 1) * 16);
        const uint32_t aXor = (uint32_t)((aRow & 7) * 16);
        const uint32_t aB0 = (uint32_t)(aRow * 128);
        // B: two n16 blocks ([n][k] rows)
        const uint32_t bKh = (uint32_t)((g8 & 1) * 16);
        uint32_t bB0[2], bXor[2];
        #pragma unroll
        for (int nb = 0; nb < 2; nb++) {
            int bRow = nw + nb * 16 + (g8 >> 1) * 8 + r8;
            bXor[nb] = (uint32_t)((bRow & 7) * 16);
            bB0[nb] = (uint32_t)(bRow * 128);
        }

        if (tid < 64) bias_s[tid] = bias[n0t + tid];
        __syncthreads();

        for (int t = 0; t < T_STEPS; t++) {
            const int pr = t & 1, pw = 1 - pr;
            float acc[4][4], cmp[4][4];
            #pragma unroll
            for (int c = 0; c < 4; c++)
                #pragma unroll
                for (int d = 0; d < 4; d++) { acc[c][d] = 0.f; cmp[c][d] = 0.f; }

            load_chunk(sb, 0, 0, t, mt, b0, pr, tid);
            load_chunk(sb, 1, 1, t, mt, b0, pr, tid);
            #pragma unroll 1
            for (int c = 0; c < CH_TOT; c++) {
                if (c + 1 < CH_TOT) {
                    asm volatile("cp.async.wait_group 1;" ::: "memory");
                } else {
                    asm volatile("cp.async.wait_group 0;" ::: "memory");
                }
                __syncthreads();   // chunk c visible to all; stage (c+2)%3 reads (iter c-1) done
                if (c + 2 < CH_TOT) load_chunk(sb, (c + 2) % 3, c + 2, t, mt, b0, pr, tid);
                uint32_t st = sb + (uint32_t)(c % 3) * STAGE_BYTES;

                // fresh chunk accumulator (keeps per-MMA rounding at chunk scale)
                float sub[4][4];
                #pragma unroll
                for (int cc = 0; cc < 4; cc++)
                    #pragma unroll
                    for (int d = 0; d < 4; d++) sub[cc][d] = 0.f;

                #pragma unroll
                for (int ks = 0; ks < 4; ks++) {
                    const uint32_t ka = ((uint32_t)(ks * 32) + aKh) ^ aXor;
                    uint32_t ah[4], am[4];
                    uint32_t bh[2][4], bm[2][4];
                    {
                        uint32_t ra = st + aB0 + ka;
                        LDSM4(ah[0], ah[1], ah[2], ah[3], ra + A_HI);
                        LDSM4(am[0], am[1], am[2], am[3], ra + A_MI);
                    }
                    #pragma unroll
                    for (int nb = 0; nb < 2; nb++) {
                        uint32_t rb = st + bB0[nb] + (((uint32_t)(ks * 32) + bKh) ^ bXor[nb]);
                        LDSM4(bh[nb][0], bh[nb][1], bh[nb][2], bh[nb][3], rb + B_HI);
                        LDSM4(bm[nb][0], bm[nb][1], bm[nb][2], bm[nb][3], rb + B_MI);
                    }
                    #pragma unroll
                    for (int nb = 0; nb < 2; nb++)
                        #pragma unroll
                        for (int h = 0; h < 2; h++) {
                            float* d = sub[nb * 2 + h];
                            MMA(d, ah, &bh[nb][h * 2]);   // hh
                            MMA(d, ah, &bm[nb][h * 2]);   // hm
                            MMA(d, am, &bh[nb][h * 2]);   // mh
                        }
                }

                // Kahan-fold chunk accumulator into running total
                #pragma unroll
                for (int cc = 0; cc < 4; cc++)
                    #pragma unroll
                    for (int d = 0; d < 4; d++) {
                        float y = sub[cc][d] - cmp[cc][d];
                        float tt = acc[cc][d] + y;
                        cmp[cc][d] = (tt - acc[cc][d]) - y;
                        acc[cc][d] = tt;
                    }
            }
            __syncthreads();   // all warps done with last stages before dsm overwrite path

            // fragments -> dsm[n][b] (stride 72)
            {
                const int mr = lane >> 2, bc = (lane & 3) * 2;
                #pragma unroll
                for (int nf = 0; nf < 4; nf++) {
                    int m = mw + mr;
                    int bcol = nw + nf * 8 + bc;
                    *(float2*)&dsm[m * 72 + bcol] = make_float2(acc[nf][0], acc[nf][1]);
                    *(float2*)&dsm[(m + 8) * 72 + bcol] = make_float2(acc[nf][2], acc[nf][3]);
                }
            }
            __syncthreads();

            // ---- epilogue: batch-major state update (4 quadrants of 16 n) ----
            {
                const int bl2 = tid & 63, q = tid >> 6;
                const int b = b0 + bl2, nl0 = q * 16;
                float* __restrict__ hp = g_h + (size_t)b * N_TOT + n0t + nl0;
                const float* __restrict__ nz =
                    noise + ((size_t)t * BATCH + b) * N_TOT + n0t + nl0;
                const float* __restrict__ d0 = isES ?
                    g_rd[pr] + (size_t)b * 2048 + g * 1024 + (m0 + nl0) : nullptr;
                const float* __restrict__ d1 = isES ? d0 + 512 : nullptr;
                float* __restrict__ rdw = isDend ?
                    g_rd[pw] + (size_t)b * 2048 + g * 1024 + (m0 - 512) + nl0 : nullptr;
                const int k0 = g * 896 + (m0 < 512 ? m0 : 512 + (m0 - 1536)) + nl0;
                bf16* __restrict__ rhw = g_rHi[pw] + (size_t)b * K_CMP + k0;
                bf16* __restrict__ rmw = g_rMi[pw] + (size_t)b * K_CMP + k0;
                #pragma unroll
                for (int i = 0; i < 16; i += 4) {
                    float4 hv = *(const float4*)&hp[i];
                    float4 nv = *(const float4*)&nz[i];
                    float tv[4], hn[4];
                    #pragma unroll
                    for (int j = 0; j < 4; j++)
                        tv[j] = dsm[(nl0 + i + j) * 72 + bl2] + bias_s[nl0 + i + j];
                    if (isES) {
                        float4 a0 = *(const float4*)&d0[i];
                        float4 a1 = *(const float4*)&d1[i];
                        tv[0] += a0.x + a1.x; tv[1] += a0.y + a1.y;
                        tv[2] += a0.z + a1.z; tv[3] += a0.w + a1.w;
                    }
                    hn[0] = 0.8f * hv.x + DECAY * tv[0] + NOISE_SCALE * nv.x;
                    hn[1] = 0.8f * hv.y + DECAY * tv[1] + NOISE_SCALE * nv.y;
                    hn[2] = 0.8f * hv.z + DECAY * tv[2] + NOISE_SCALE * nv.z;
                    hn[3] = 0.8f * hv.w + DECAY * tv[3] + NOISE_SCALE * nv.w;
                    *(float4*)&hp[i] = make_float4(hn[0], hn[1], hn[2], hn[3]);
                    if (isDend) {
                        *(float4*)&rdw[i] = make_float4(tanhf(hn[0]), tanhf(hn[1]),
                                                        tanhf(hn[2]), tanhf(hn[3]));
                    } else {
                        uint32_t hw[2], mw2[2];
                        #pragma unroll
                        for (int p = 0; p < 2; p++) {
                            float r0 = fmaxf(hn[p * 2], 0.f), r1 = fmaxf(hn[p * 2 + 1], 0.f);
                            bf16 h0b, m0b, h1b, m1b;
                            split2(r0, h0b, m0b);
                            split2(r1, h1b, m1b);
                            hw[p] = (uint32_t)__bfloat16_as_ushort(h0b) |
                                    ((uint32_t)__bfloat16_as_ushort(h1b) << 16);
                            mw2[p] = (uint32_t)__bfloat16_as_ushort(m0b) |
                                     ((uint32_t)__bfloat16_as_ushort(m1b) << 16);
                        }
                        *(uint2*)&rhw[i] = make_uint2(hw[0], hw[1]);
                        *(uint2*)&rmw[i] = make_uint2(mw2[0], mw2[1]);
                    }
                }
            }
            grid_barrier(gen); gen++;
        }
    } else {
        const int o = bx - NB_GEMM;
        float* wcol = (float*)sm;
        for (int s = tid; s < N_ES; s += NTHR) wcol[s] = w_out[(size_t)s * N_OUT + o];
        __syncthreads();
        for (int t = 0; t <= T_STEPS; t++) {
            if (t > 0 && tid < BATCH) {
                const int tt = t - 1, buf = (tt + 1) & 1;
                const bf16* __restrict__ rh = g_rHi[buf] + (size_t)tid * K_CMP;
                const bf16* __restrict__ rm = g_rMi[buf] + (size_t)tid * K_CMP;
                float acc = 0.f;
                #pragma unroll 8
                for (int s = 0; s < N_ES; s++)
                    acc += (__bfloat162float(rh[s]) + __bfloat162float(rm[s])) * wcol[s];
                out[((size_t)tt * BATCH + tid) * N_OUT + o] = acc;
            }
            if (t < T_STEPS) { grid_barrier(gen); gen++; }
        }
    }
}

extern "C" void kernel_launch(void* const* d_in, const int* in_sizes, int n_in,
                              void* d_out, int out_size) {
    const float* x     = (const float*)d_in[0];
    const float* noise = (const float*)d_in[1];
    const float* w_rec = (const float*)d_in[2];
    const float* w_in  = (const float*)d_in[3];
    const float* w_out = (const float*)d_in[4];
    const float* bias  = (const float*)d_in[5];
    const float* h0    = (const float*)d_in[6];
    const float* mask  = (const float*)d_in[7];
    float* out = (float*)d_out;
    (void)in_sizes; (void)n_in; (void)out_size;

    cudaFuncSetAttribute(rollout_kernel, cudaFuncAttributeMaxDynamicSharedMemorySize, SMEM_DYN);

    { dim3 g(K_CMP / 32, N_TOT / 32); prep_w_kernel<<<g, dim3(32, 8)>>>(w_rec, mask); }
    { size_t n = (size_t)N_IN * N_TOT; prep_win_kernel<<<(int)((n + 255) / 256), 256>>>(w_in); }
    { size_t n = (size_t)T_STEPS * BATCH * N_IN; prep_x_kernel<<<(int)((n + 255) / 256), 256>>>(x); }
    { size_t n = (size_t)BATCH * N_TOT; init_state_kernel<<<(int)((n + 255) / 256), 256>>>(h0); }
    reset_barrier_kernel<<<1, 1>>>();

    rollout_kernel<<<NBLK, NTHR, SMEM_DYN>>>(noise, bias, w_out, out);
}

// round 16
// speedup vs baseline: 3.1798x; 1.0331x over previous
#include <cuda_runtime.h>
#include <cuda_bf16.h>
#include <cstdint>
#include <cstddef>

#define T_STEPS 200
#define BATCH 128
#define N_IN 64
#define N_OUT 10
#define N_ES 512
#define REGION 1920
#define N_TOT 3840
#define K_CMP 1792
#define NB_GEMM 120
#define NBLK 130
#define NTHR 512
#define CH_TOT 29            /* 28 recurrent K64 chunks + 1 input chunk */
#define DECAY 0.2f
#define NOISE_SCALE 0.0063245553203367585f

#define STAGE_BYTES 32768
#define A_HI 0
#define A_MI 8192
#define B_HI 16384
#define B_MI 24576
#define DSM_OFF 98304        /* 64 x 72 floats = 18432 B */
#define BIAS_OFF 116736
#define SMEM_DYN 117248

typedef unsigned long long u64;
typedef __nv_bfloat16 bf16;

__device__ __align__(16) bf16  g_WtHi[(size_t)N_TOT * K_CMP];
__device__ __align__(16) bf16  g_WtMi[(size_t)N_TOT * K_CMP];
__device__ __align__(16) bf16  g_WinHi[(size_t)N_TOT * N_IN];
__device__ __align__(16) bf16  g_WinMi[(size_t)N_TOT * N_IN];
__device__ __align__(16) bf16  g_xHi[(size_t)T_STEPS * BATCH * N_IN];
__device__ __align__(16) bf16  g_xMi[(size_t)T_STEPS * BATCH * N_IN];
__device__ __align__(16) bf16  g_rHi[2][(size_t)BATCH * K_CMP];
__device__ __align__(16) bf16  g_rMi[2][(size_t)BATCH * K_CMP];
__device__ __align__(16) float g_rd[2][(size_t)BATCH * 2048];
__device__ __align__(16) float g_h[(size_t)BATCH * N_TOT];
__device__ unsigned g_bar_count, g_bar_gen;

__device__ __forceinline__ uint32_t smem_u32(const void* p) {
    uint32_t a;
    asm("{ .reg .u64 t; cvta.to.shared.u64 t, %1; cvt.u32.u64 %0, t; }" : "=r"(a) : "l"(p));
    return a;
}
#define SWZ(o) ((o) ^ (((o) >> 3) & 0x70))
__device__ __forceinline__ void cp16(uint32_t d, const void* s) {
    asm volatile("cp.async.cg.shared.global [%0], [%1], 16;" :: "r"(d), "l"(s));
}
#define LDSM4(r0, r1, r2, r3, a) \
    asm volatile("ldmatrix.sync.aligned.m8n8.x4.shared.b16 {%0,%1,%2,%3}, [%4];" \
                 : "=r"(r0), "=r"(r1), "=r"(r2), "=r"(r3) : "r"(a))
#define MMA(d, a, b) \
    asm volatile("mma.sync.aligned.m16n8k16.row.col.f32.bf16.bf16.f32 " \
                 "{%0,%1,%2,%3},{%4,%5,%6,%7},{%8,%9},{%0,%1,%2,%3};" \
                 : "+f"((d)[0]), "+f"((d)[1]), "+f"((d)[2]), "+f"((d)[3]) \
                 : "r"((a)[0]), "r"((a)[1]), "r"((a)[2]), "r"((a)[3]), \
                   "r"((b)[0]), "r"((b)[1]))

__device__ __forceinline__ void split2(float v, bf16& h, bf16& m) {
    h = __float2bfloat16(v);
    m = __float2bfloat16(v - __bfloat162float(h));
}
__device__ __forceinline__ int korig_add(int k) {
    return (k < 512) ? 0 : (k < 1408 ? 1024 : 2048);
}

// ---------- preprocessing ----------
__global__ void prep_w_kernel(const float* __restrict__ w_rec, const float* __restrict__ mask) {
    __shared__ float tile[32][33];
    int k0 = blockIdx.x * 32, n0 = blockIdx.y * 32;
    int orig0 = k0 + korig_add(k0);
    #pragma unroll
    for (int i = 0; i < 4; i++) {
        int r = threadIdx.y + i * 8;
        size_t s = (size_t)(orig0 + r) * N_TOT + n0 + threadIdx.x;
        tile[r][threadIdx.x] = fabsf(w_rec[s]) * mask[s];
    }
    __syncthreads();
    #pragma unroll
    for (int i = 0; i < 4; i++) {
        int rr = threadIdx.y + i * 8;
        bf16 h, m;
        split2(tile[threadIdx.x][rr], h, m);
        size_t d = (size_t)(n0 + rr) * K_CMP + k0 + threadIdx.x;
        g_WtHi[d] = h; g_WtMi[d] = m;
    }
}
__global__ void prep_win_kernel(const float* __restrict__ w_in) {
    size_t i = (size_t)blockIdx.x * blockDim.x + threadIdx.x;
    if (i >= (size_t)N_IN * N_TOT) return;
    int kin = (int)(i / N_TOT), n = (int)(i - (size_t)kin * N_TOT);
    bf16 h, m;
    split2(w_in[i], h, m);
    size_t d = (size_t)n * N_IN + kin;
    g_WinHi[d] = h; g_WinMi[d] = m;
}
__global__ void prep_x_kernel(const float* __restrict__ x) {
    size_t i = (size_t)blockIdx.x * blockDim.x + threadIdx.x;
    if (i >= (size_t)T_STEPS * BATCH * N_IN) return;
    bf16 h, m;
    split2(x[i], h, m);
    g_xHi[i] = h; g_xMi[i] = m;
}
__global__ void init_state_kernel(const float* __restrict__ h0) {
    size_t i = (size_t)blockIdx.x * blockDim.x + threadIdx.x;
    if (i >= (size_t)BATCH * N_TOT) return;
    int n = (int)(i % N_TOT), b = (int)(i / N_TOT);
    float hv = h0[i];
    g_h[i] = hv;
    int g = n / REGION, m = n - g * REGION;
    if (m >= 512 && m < 1536) {
        g_rd[0][(size_t)b * 2048 + g * 1024 + (m - 512)] = tanhf(hv);
    } else {
        float r = fmaxf(hv, 0.f);
        int k = g * 896 + (m < 512 ? m : 512 + (m - 1536));
        bf16 hh, mm;
        split2(r, hh, mm);
        size_t d = (size_t)b * K_CMP + k;
        g_rHi[0][d] = hh; g_rMi[0][d] = mm;
    }
}
__global__ void reset_barrier_kernel() { g_bar_count = 0u; g_bar_gen = 0u; }

__device__ __forceinline__ void grid_barrier(unsigned gen) {
    __syncthreads();
    if (threadIdx.x == 0) {
        __threadfence();
        if (atomicAdd(&g_bar_count, 1u) == NBLK - 1u) {
            g_bar_count = 0u;
            __threadfence();
            asm volatile("st.release.gpu.u32 [%0], %1;" :: "l"(&g_bar_gen), "r"(gen + 1u) : "memory");
        } else {
            unsigned cur;
            do {
                __nanosleep(64);
                asm volatile("ld.acquire.gpu.u32 %0, [%1];" : "=r"(cur) : "l"(&g_bar_gen) : "memory");
            } while (cur == gen);
        }
    }
    __syncthreads();
}

// one K64 chunk into stage stg (512 threads): 4 streams x 64 rows x 128B, 4 cp16/thread
__device__ __forceinline__ void load_chunk(uint32_t sb, int stg, int c, int t,
                                           int mt, int b0, int pr, int tid) {
    uint32_t st = sb + stg * STAGE_BYTES;
    int row = tid >> 3, s = tid & 7;
    const bf16 *Ah, *Am, *Bh, *Bm;
    if (c < CH_TOT - 1) {
        size_t ao = (size_t)(mt * 64 + row) * K_CMP + c * 64;
        Ah = g_WtHi + ao; Am = g_WtMi + ao;
        size_t bo = (size_t)(b0 + row) * K_CMP + c * 64;
        Bh = g_rHi[pr] + bo; Bm = g_rMi[pr] + bo;
    } else {
        size_t ao = (size_t)(mt * 64 + row) * N_IN;
        Ah = g_WinHi + ao; Am = g_WinMi + ao;
        size_t bo = ((size_t)t * BATCH + b0 + row) * N_IN;
        Bh = g_xHi + bo; Bm = g_xMi + bo;
    }
    uint32_t d = SWZ((uint32_t)(row * 128 + s * 16));
    cp16(st + A_HI + d, Ah + s * 8);
    cp16(st + A_MI + d, Am + s * 8);
    cp16(st + B_HI + d, Bh + s * 8);
    cp16(st + B_MI + d, Bm + s * 8);
    asm volatile("cp.async.commit_group;" ::: "memory");
}

__global__ void __launch_bounds__(NTHR, 1)
rollout_kernel(const float* __restrict__ noise, const float* __restrict__ bias,
               const float* __restrict__ w_out, float* __restrict__ out) {
    extern __shared__ __align__(1024) char sm[];
    uint32_t sb = smem_u32(sm);
    const int tid = threadIdx.x, bx = blockIdx.x;
    unsigned gen = 0;

    if (bx < NB_GEMM) {
        const int mt = bx >> 1, b0 = (bx & 1) * 64;
        const int n0t = mt * 64;
        const int g = n0t / REGION, m0 = n0t - g * REGION;
        const bool isES = (m0 < 512), isDend = (m0 >= 512 && m0 < 1536);
        float* dsm = (float*)(sm + DSM_OFF);
        float* bias_s = (float*)(sm + BIAS_OFF);

        const int wid = tid >> 5, lane = tid & 31;
        const int mw = (wid & 3) * 16, nw = (wid >> 2) * 16;   // 4 m-tiles x 4 n-tiles
        const int g8 = lane >> 3, r8 = lane & 7;
        // A: one m16k16 row-major frag per warp
        const int aRow = mw + (g8 & 1) * 8 + r8;
        const uint32_t aKh = (uint32_t)((g8 >> 1) * 16);
        const uint32_t aXor = (uint32_t)((aRow & 7) * 16);
        const uint32_t aB0 = (uint32_t)(aRow * 128);
        // B: one n16 block ([n][k] rows)
        const int bRow = nw + (g8 >> 1) * 8 + r8;
        const uint32_t bKh = (uint32_t)((g8 & 1) * 16);
        const uint32_t bXor = (uint32_t)((bRow & 7) * 16);
        const uint32_t bB0 = (uint32_t)(bRow * 128);

        if (tid < 64) bias_s[tid] = bias[n0t + tid];
        __syncthreads();

        for (int t = 0; t < T_STEPS; t++) {
            const int pr = t & 1, pw = 1 - pr;
            float acc[2][4], cmp[2][4];
            #pragma unroll
            for (int c = 0; c < 2; c++)
                #pragma unroll
                for (int d = 0; d < 4; d++) { acc[c][d] = 0.f; cmp[c][d] = 0.f; }

            load_chunk(sb, 0, 0, t, mt, b0, pr, tid);
            load_chunk(sb, 1, 1, t, mt, b0, pr, tid);
            #pragma unroll 1
            for (int c = 0; c < CH_TOT; c++) {
                if (c + 1 < CH_TOT) {
                    asm volatile("cp.async.wait_group 1;" ::: "memory");
                } else {
                    asm volatile("cp.async.wait_group 0;" ::: "memory");
                }
                __syncthreads();   // chunk c visible; stage (c+2)%3 reads (iter c-1) done
                if (c + 2 < CH_TOT) load_chunk(sb, (c + 2) % 3, c + 2, t, mt, b0, pr, tid);
                uint32_t st = sb + (uint32_t)(c % 3) * STAGE_BYTES;

                // fresh chunk accumulator (keeps per-MMA rounding at chunk scale)
                float sub[2][4];
                #pragma unroll
                for (int cc = 0; cc < 2; cc++)
                    #pragma unroll
                    for (int d = 0; d < 4; d++) sub[cc][d] = 0.f;

                #pragma unroll
                for (int ks = 0; ks < 4; ks++) {
                    const uint32_t ka = ((uint32_t)(ks * 32) + aKh) ^ aXor;
                    const uint32_t kb = ((uint32_t)(ks * 32) + bKh) ^ bXor;
                    uint32_t ah[4], am[4], bh[4], bm[4];
                    {
                        uint32_t ra = st + aB0 + ka;
                        LDSM4(ah[0], ah[1], ah[2], ah[3], ra + A_HI);
                        LDSM4(am[0], am[1], am[2], am[3], ra + A_MI);
                    }
                    {
                        uint32_t rb = st + bB0 + kb;
                        LDSM4(bh[0], bh[1], bh[2], bh[3], rb + B_HI);
                        LDSM4(bm[0], bm[1], bm[2], bm[3], rb + B_MI);
                    }
                    #pragma unroll
                    for (int h = 0; h < 2; h++) {
                        float* d = sub[h];
                        MMA(d, ah, &bh[h * 2]);   // hh
                        MMA(d, ah, &bm[h * 2]);   // hm
                        MMA(d, am, &bh[h * 2]);   // mh
                    }
                }

                // Kahan-fold chunk accumulator into running total
                #pragma unroll
                for (int cc = 0; cc < 2; cc++)
                    #pragma unroll
                    for (int d = 0; d < 4; d++) {
                        float y = sub[cc][d] - cmp[cc][d];
                        float tt = acc[cc][d] + y;
                        cmp[cc][d] = (tt - acc[cc][d]) - y;
                        acc[cc][d] = tt;
                    }
            }
            __syncthreads();   // all warps done with last stages before dsm write

            // fragments -> dsm[n][b] (stride 72)
            {
                const int mr = lane >> 2, bc = (lane & 3) * 2;
                #pragma unroll
                for (int nf = 0; nf < 2; nf++) {
                    int m = mw + mr;
                    int bcol = nw + nf * 8 + bc;
                    *(float2*)&dsm[m * 72 + bcol] = make_float2(acc[nf][0], acc[nf][1]);
                    *(float2*)&dsm[(m + 8) * 72 + bcol] = make_float2(acc[nf][2], acc[nf][3]);
                }
            }
            __syncthreads();

            // ---- epilogue: batch-major state update (8 groups of 8 n) ----
            {
                const int bl2 = tid & 63, q = tid >> 6;
                const int b = b0 + bl2, nl0 = q * 8;
                float* __restrict__ hp = g_h + (size_t)b * N_TOT + n0t + nl0;
                const float* __restrict__ nz =
                    noise + ((size_t)t * BATCH + b) * N_TOT + n0t + nl0;
                const float* __restrict__ d0 = isES ?
                    g_rd[pr] + (size_t)b * 2048 + g * 1024 + (m0 + nl0) : nullptr;
                const float* __restrict__ d1 = isES ? d0 + 512 : nullptr;
                float* __restrict__ rdw = isDend ?
                    g_rd[pw] + (size_t)b * 2048 + g * 1024 + (m0 - 512) + nl0 : nullptr;
                const int k0 = g * 896 + (m0 < 512 ? m0 : 512 + (m0 - 1536)) + nl0;
                bf16* __restrict__ rhw = g_rHi[pw] + (size_t)b * K_CMP + k0;
                bf16* __restrict__ rmw = g_rMi[pw] + (size_t)b * K_CMP + k0;
                #pragma unroll
                for (int i = 0; i < 8; i += 4) {
                    float4 hv = *(const float4*)&hp[i];
                    float4 nv = *(const float4*)&nz[i];
                    float tv[4], hn[4];
                    #pragma unroll
                    for (int j = 0; j < 4; j++)
                        tv[j] = dsm[(nl0 + i + j) * 72 + bl2] + bias_s[nl0 + i + j];
                    if (isES) {
                        float4 a0 = *(const float4*)&d0[i];
                        float4 a1 = *(const float4*)&d1[i];
                        tv[0] += a0.x + a1.x; tv[1] += a0.y + a1.y;
                        tv[2] += a0.z + a1.z; tv[3] += a0.w + a1.w;
                    }
                    hn[0] = 0.8f * hv.x + DECAY * tv[0] + NOISE_SCALE * nv.x;
                    hn[1] = 0.8f * hv.y + DECAY * tv[1] + NOISE_SCALE * nv.y;
                    hn[2] = 0.8f * hv.z + DECAY * tv[2] + NOISE_SCALE * nv.z;
                    hn[3] = 0.8f * hv.w + DECAY * tv[3] + NOISE_SCALE * nv.w;
                    *(float4*)&hp[i] = make_float4(hn[0], hn[1], hn[2], hn[3]);
                    if (isDend) {
                        *(float4*)&rdw[i] = make_float4(tanhf(hn[0]), tanhf(hn[1]),
                                                        tanhf(hn[2]), tanhf(hn[3]));
                    } else {
                        uint32_t hw[2], mw2[2];
                        #pragma unroll
                        for (int p = 0; p < 2; p++) {
                            float r0 = fmaxf(hn[p * 2], 0.f), r1 = fmaxf(hn[p * 2 + 1], 0.f);
                            bf16 h0b, m0b, h1b, m1b;
                            split2(r0, h0b, m0b);
                            split2(r1, h1b, m1b);
                            hw[p] = (uint32_t)__bfloat16_as_ushort(h0b) |
                                    ((uint32_t)__bfloat16_as_ushort(h1b) << 16);
                            mw2[p] = (uint32_t)__bfloat16_as_ushort(m0b) |
                                     ((uint32_t)__bfloat16_as_ushort(m1b) << 16);
                        }
                        *(uint2*)&rhw[i] = make_uint2(hw[0], hw[1]);
                        *(uint2*)&rmw[i] = make_uint2(mw2[0], mw2[1]);
                    }
                }
            }
            grid_barrier(gen); gen++;
        }
    } else {
        const int o = bx - NB_GEMM;
        float* wcol = (float*)sm;
        for (int s = tid; s < N_ES; s += NTHR) wcol[s] = w_out[(size_t)s * N_OUT + o];
        __syncthreads();
        for (int t = 0; t <= T_STEPS; t++) {
            if (t > 0 && tid < BATCH) {
                const int tt = t - 1, buf = (tt + 1) & 1;
                const uint4* __restrict__ rh =
                    (const uint4*)(g_rHi[buf] + (size_t)tid * K_CMP);
                const uint4* __restrict__ rm =
                    (const uint4*)(g_rMi[buf] + (size_t)tid * K_CMP);
                float acc = 0.f;
                #pragma unroll 4
                for (int v = 0; v < N_ES / 8; v++) {
                    uint4 ph = rh[v], pm = rm[v];
                    const bf16* eh = (const bf16*)&ph;
                    const bf16* em = (const bf16*)&pm;
                    #pragma unroll
                    for (int e = 0; e < 8; e++)
                        acc += (__bfloat162float(eh[e]) + __bfloat162float(em[e]))
                               * wcol[v * 8 + e];
                }
                out[((size_t)tt * BATCH + tid) * N_OUT + o] = acc;
            }
            if (t < T_STEPS) { grid_barrier(gen); gen++; }
        }
    }
}

extern "C" void kernel_launch(void* const* d_in, const int* in_sizes, int n_in,
                              void* d_out, int out_size) {
    const float* x     = (const float*)d_in[0];
    const float* noise = (const float*)d_in[1];
    const float* w_rec = (const float*)d_in[2];
    const float* w_in  = (const float*)d_in[3];
    const float* w_out = (const float*)d_in[4];
    const float* bias  = (const float*)d_in[5];
    const float* h0    = (const float*)d_in[6];
    const float* mask  = (const float*)d_in[7];
    float* out = (float*)d_out;
    (void)in_sizes; (void)n_in; (void)out_size;

    cudaFuncSetAttribute(rollout_kernel, cudaFuncAttributeMaxDynamicSharedMemorySize, SMEM_DYN);

    { dim3 g(K_CMP / 32, N_TOT / 32); prep_w_kernel<<<g, dim3(32, 8)>>>(w_rec, mask); }
    { size_t n = (size_t)N_IN * N_TOT; prep_win_kernel<<<(int)((n + 255) / 256), 256>>>(w_in); }
    { size_t n = (size_t)T_STEPS * BATCH * N_IN; prep_x_kernel<<<(int)((n + 255) / 256), 256>>>(x); }
    { size_t n = (size_t)BATCH * N_TOT; init_state_kernel<<<(int)((n + 255) / 256), 256>>>(h0); }
    reset_barrier_kernel<<<1, 1>>>();

    rollout_kernel<<<NBLK, NTHR, SMEM_DYN>>>(noise, bias, w_out, out);
}

// round 17
// speedup vs baseline: 3.5392x; 1.1130x over previous
#include <cuda_runtime.h>
#include <cuda_bf16.h>
#include <cstdint>
#include <cstddef>

#define T_STEPS 200
#define BATCH 128
#define N_IN 64
#define N_OUT 10
#define N_ES 512
#define REGION 1920
#define N_TOT 3840
#define K_CMP 1792
#define NB_GEMM 120
#define NBLK 130
#define NTHR 512
#define CH_TOT 29            /* 28 recurrent K64 chunks + 1 input chunk */
#define DECAY 0.2f
#define NOISE_SCALE 0.0063245553203367585f

#define STAGE_BYTES 32768
#define A_HI 0
#define A_MI 8192
#define B_HI 16384
#define B_MI 24576
#define DSM_OFF 131072       /* dedicated: 64 x 72 floats = 18432 B */
#define BIAS_OFF 149504
#define SMEM_DYN 150016

typedef unsigned long long u64;
typedef __nv_bfloat16 bf16;

__device__ __align__(16) bf16  g_WtHi[(size_t)N_TOT * K_CMP];
__device__ __align__(16) bf16  g_WtMi[(size_t)N_TOT * K_CMP];
__device__ __align__(16) bf16  g_WinHi[(size_t)N_TOT * N_IN];
__device__ __align__(16) bf16  g_WinMi[(size_t)N_TOT * N_IN];
__device__ __align__(16) bf16  g_xHi[(size_t)T_STEPS * BATCH * N_IN];
__device__ __align__(16) bf16  g_xMi[(size_t)T_STEPS * BATCH * N_IN];
__device__ __align__(16) bf16  g_rHi[2][(size_t)BATCH * K_CMP];
__device__ __align__(16) bf16  g_rMi[2][(size_t)BATCH * K_CMP];
__device__ __align__(16) float g_rd[2][(size_t)BATCH * 2048];
__device__ __align__(16) float g_h[(size_t)BATCH * N_TOT];
__device__ unsigned g_bar_count, g_bar_gen;

__device__ __forceinline__ uint32_t smem_u32(const void* p) {
    uint32_t a;
    asm("{ .reg .u64 t; cvta.to.shared.u64 t, %1; cvt.u32.u64 %0, t; }" : "=r"(a) : "l"(p));
    return a;
}
#define SWZ(o) ((o) ^ (((o) >> 3) & 0x70))
__device__ __forceinline__ void cp16(uint32_t d, const void* s) {
    asm volatile("cp.async.cg.shared.global [%0], [%1], 16;" :: "r"(d), "l"(s));
}
#define LDSM4(r0, r1, r2, r3, a) \
    asm volatile("ldmatrix.sync.aligned.m8n8.x4.shared.b16 {%0,%1,%2,%3}, [%4];" \
                 : "=r"(r0), "=r"(r1), "=r"(r2), "=r"(r3) : "r"(a))
#define MMA(d, a, b) \
    asm volatile("mma.sync.aligned.m16n8k16.row.col.f32.bf16.bf16.f32 " \
                 "{%0,%1,%2,%3},{%4,%5,%6,%7},{%8,%9},{%0,%1,%2,%3};" \
                 : "+f"((d)[0]), "+f"((d)[1]), "+f"((d)[2]), "+f"((d)[3]) \
                 : "r"((a)[0]), "r"((a)[1]), "r"((a)[2]), "r"((a)[3]), \
                   "r"((b)[0]), "r"((b)[1]))

__device__ __forceinline__ void split2(float v, bf16& h, bf16& m) {
    h = __float2bfloat16(v);
    m = __float2bfloat16(v - __bfloat162float(h));
}
__device__ __forceinline__ int korig_add(int k) {
    return (k < 512) ? 0 : (k < 1408 ? 1024 : 2048);
}

// ---------- preprocessing ----------
__global__ void prep_w_kernel(const float* __restrict__ w_rec, const float* __restrict__ mask) {
    __shared__ float tile[32][33];
    int k0 = blockIdx.x * 32, n0 = blockIdx.y * 32;
    int orig0 = k0 + korig_add(k0);
    #pragma unroll
    for (int i = 0; i < 4; i++) {
        int r = threadIdx.y + i * 8;
        size_t s = (size_t)(orig0 + r) * N_TOT + n0 + threadIdx.x;
        tile[r][threadIdx.x] = fabsf(w_rec[s]) * mask[s];
    }
    __syncthreads();
    #pragma unroll
    for (int i = 0; i < 4; i++) {
        int rr = threadIdx.y + i * 8;
        bf16 h, m;
        split2(tile[threadIdx.x][rr], h, m);
        size_t d = (size_t)(n0 + rr) * K_CMP + k0 + threadIdx.x;
        g_WtHi[d] = h; g_WtMi[d] = m;
    }
}
__global__ void prep_win_kernel(const float* __restrict__ w_in) {
    size_t i = (size_t)blockIdx.x * blockDim.x + threadIdx.x;
    if (i >= (size_t)N_IN * N_TOT) return;
    int kin = (int)(i / N_TOT), n = (int)(i - (size_t)kin * N_TOT);
    bf16 h, m;
    split2(w_in[i], h, m);
    size_t d = (size_t)n * N_IN + kin;
    g_WinHi[d] = h; g_WinMi[d] = m;
}
__global__ void prep_x_kernel(const float* __restrict__ x) {
    size_t i = (size_t)blockIdx.x * blockDim.x + threadIdx.x;
    if (i >= (size_t)T_STEPS * BATCH * N_IN) return;
    bf16 h, m;
    split2(x[i], h, m);
    g_xHi[i] = h; g_xMi[i] = m;
}
__global__ void init_state_kernel(const float* __restrict__ h0) {
    size_t i = (size_t)blockIdx.x * blockDim.x + threadIdx.x;
    if (i >= (size_t)BATCH * N_TOT) return;
    int n = (int)(i % N_TOT), b = (int)(i / N_TOT);
    float hv = h0[i];
    g_h[i] = hv;
    int g = n / REGION, m = n - g * REGION;
    if (m >= 512 && m < 1536) {
        g_rd[0][(size_t)b * 2048 + g * 1024 + (m - 512)] = tanhf(hv);
    } else {
        float r = fmaxf(hv, 0.f);
        int k = g * 896 + (m < 512 ? m : 512 + (m - 1536));
        bf16 hh, mm;
        split2(r, hh, mm);
        size_t d = (size_t)b * K_CMP + k;
        g_rHi[0][d] = hh; g_rMi[0][d] = mm;
    }
}
__global__ void reset_barrier_kernel() { g_bar_count = 0u; g_bar_gen = 0u; }

__device__ __forceinline__ void grid_barrier(unsigned gen) {
    __syncthreads();
    if (threadIdx.x == 0) {
        __threadfence();
        if (atomicAdd(&g_bar_count, 1u) == NBLK - 1u) {
            g_bar_count = 0u;
            __threadfence();
            asm volatile("st.release.gpu.u32 [%0], %1;" :: "l"(&g_bar_gen), "r"(gen + 1u) : "memory");
        } else {
            unsigned cur;
            do {
                __nanosleep(64);
                asm volatile("ld.acquire.gpu.u32 %0, [%1];" : "=r"(cur) : "l"(&g_bar_gen) : "memory");
            } while (cur == gen);
        }
    }
    __syncthreads();
}

// one K64 chunk into stage stg (512 threads): 4 streams x 64 rows x 128B, 4 cp16/thread
__device__ __forceinline__ void load_chunk(uint32_t sb, int stg, int c, int t,
                                           int mt, int b0, int pr, int tid) {
    uint32_t st = sb + stg * STAGE_BYTES;
    int row = tid >> 3, s = tid & 7;
    const bf16 *Ah, *Am, *Bh, *Bm;
    if (c < CH_TOT - 1) {
        size_t ao = (size_t)(mt * 64 + row) * K_CMP + c * 64;
        Ah = g_WtHi + ao; Am = g_WtMi + ao;
        size_t bo = (size_t)(b0 + row) * K_CMP + c * 64;
        Bh = g_rHi[pr] + bo; Bm = g_rMi[pr] + bo;
    } else {
        size_t ao = (size_t)(mt * 64 + row) * N_IN;
        Ah = g_WinHi + ao; Am = g_WinMi + ao;
        size_t bo = ((size_t)t * BATCH + b0 + row) * N_IN;
        Bh = g_xHi + bo; Bm = g_xMi + bo;
    }
    uint32_t d = SWZ((uint32_t)(row * 128 + s * 16));
    cp16(st + A_HI + d, Ah + s * 8);
    cp16(st + A_MI + d, Am + s * 8);
    cp16(st + B_HI + d, Bh + s * 8);
    cp16(st + B_MI + d, Bm + s * 8);
    asm volatile("cp.async.commit_group;" ::: "memory");
}

__global__ void __launch_bounds__(NTHR, 1)
rollout_kernel(const float* __restrict__ noise, const float* __restrict__ bias,
               const float* __restrict__ w_out, float* __restrict__ out) {
    extern __shared__ __align__(1024) char sm[];
    uint32_t sb = smem_u32(sm);
    const int tid = threadIdx.x, bx = blockIdx.x;
    unsigned gen = 0;

    if (bx < NB_GEMM) {
        const int mt = bx >> 1, b0 = (bx & 1) * 64;
        const int n0t = mt * 64;
        const int g = n0t / REGION, m0 = n0t - g * REGION;
        const bool isES = (m0 < 512), isDend = (m0 >= 512 && m0 < 1536);
        float* dsm = (float*)(sm + DSM_OFF);
        float* bias_s = (float*)(sm + BIAS_OFF);

        const int wid = tid >> 5, lane = tid & 31;
        const int mw = (wid & 3) * 16, nw = (wid >> 2) * 16;   // 4 m-tiles x 4 n-tiles
        const int g8 = lane >> 3, r8 = lane & 7;
        // A: one m16k16 row-major frag per warp
        const int aRow = mw + (g8 & 1) * 8 + r8;
        const uint32_t aKh = (uint32_t)((g8 >> 1) * 16);
        const uint32_t aXor = (uint32_t)((aRow & 7) * 16);
        const uint32_t aB0 = (uint32_t)(aRow * 128);
        // B: one n16 block ([n][k] rows)
        const int bRow = nw + (g8 >> 1) * 8 + r8;
        const uint32_t bKh = (uint32_t)((g8 & 1) * 16);
        const uint32_t bXor = (uint32_t)((bRow & 7) * 16);
        const uint32_t bB0 = (uint32_t)(bRow * 128);

        if (tid < 64) bias_s[tid] = bias[n0t + tid];
        __syncthreads();

        for (int t = 0; t < T_STEPS; t++) {
            const int pr = t & 1, pw = 1 - pr;
            float acc[2][4], cmp[2][4];
            #pragma unroll
            for (int c = 0; c < 2; c++)
                #pragma unroll
                for (int d = 0; d < 4; d++) { acc[c][d] = 0.f; cmp[c][d] = 0.f; }

            load_chunk(sb, 0, 0, t, mt, b0, pr, tid);
            load_chunk(sb, 1, 1, t, mt, b0, pr, tid);
            #pragma unroll 1
            for (int c = 0; c < CH_TOT; c++) {
                if ((c & 1) == 0) {
                    // all pending loads (chunks <= c+1) local-done, then make visible
                    asm volatile("cp.async.wait_group 0;" ::: "memory");
                    __syncthreads();
                    // issue next two chunks; their stages were last read at iters
                    // c-2 / c-1, both before this barrier -> race-free
                    if (c + 2 < CH_TOT) load_chunk(sb, (c + 2) & 3, c + 2, t, mt, b0, pr, tid);
                    if (c + 3 < CH_TOT) load_chunk(sb, (c + 3) & 3, c + 3, t, mt, b0, pr, tid);
                }
                uint32_t st = sb + (uint32_t)(c & 3) * STAGE_BYTES;

                // fresh chunk accumulator (keeps per-MMA rounding at chunk scale)
                float sub[2][4];
                #pragma unroll
                for (int cc = 0; cc < 2; cc++)
                    #pragma unroll
                    for (int d = 0; d < 4; d++) sub[cc][d] = 0.f;

                #pragma unroll
                for (int ks = 0; ks < 4; ks++) {
                    const uint32_t ka = ((uint32_t)(ks * 32) + aKh) ^ aXor;
                    const uint32_t kb = ((uint32_t)(ks * 32) + bKh) ^ bXor;
                    uint32_t ah[4], am[4], bh[4], bm[4];
                    {
                        uint32_t ra = st + aB0 + ka;
                        LDSM4(ah[0], ah[1], ah[2], ah[3], ra + A_HI);
                        LDSM4(am[0], am[1], am[2], am[3], ra + A_MI);
                    }
                    {
                        uint32_t rb = st + bB0 + kb;
                        LDSM4(bh[0], bh[1], bh[2], bh[3], rb + B_HI);
                        LDSM4(bm[0], bm[1], bm[2], bm[3], rb + B_MI);
                    }
                    #pragma unroll
                    for (int h = 0; h < 2; h++) {
                        float* d = sub[h];
                        MMA(d, ah, &bh[h * 2]);   // hh
                        MMA(d, ah, &bm[h * 2]);   // hm
                        MMA(d, am, &bh[h * 2]);   // mh
                    }
                }

                // Kahan-fold chunk accumulator into running total
                #pragma unroll
                for (int cc = 0; cc < 2; cc++)
                    #pragma unroll
                    for (int d = 0; d < 4; d++) {
                        float y = sub[cc][d] - cmp[cc][d];
                        float tt = acc[cc][d] + y;
                        cmp[cc][d] = (tt - acc[cc][d]) - y;
                        acc[cc][d] = tt;
                    }
            }

            // fragments -> dsm[n][b] (stride 72); dsm is dedicated, per-warp slices
            // disjoint -> no barrier needed before writing
            {
                const int mr = lane >> 2, bc = (lane & 3) * 2;
                #pragma unroll
                for (int nf = 0; nf < 2; nf++) {
                    int m = mw + mr;
                    int bcol = nw + nf * 8 + bc;
                    *(float2*)&dsm[m * 72 + bcol] = make_float2(acc[nf][0], acc[nf][1]);
                    *(float2*)&dsm[(m + 8) * 72 + bcol] = make_float2(acc[nf][2], acc[nf][3]);
                }
            }
            __syncthreads();

            // ---- epilogue: batch-major state update (8 groups of 8 n) ----
            {
                const int bl2 = tid & 63, q = tid >> 6;
                const int b = b0 + bl2, nl0 = q * 8;
                float* __restrict__ hp = g_h + (size_t)b * N_TOT + n0t + nl0;
                const float* __restrict__ nz =
                    noise + ((size_t)t * BATCH + b) * N_TOT + n0t + nl0;
                const float* __restrict__ d0 = isES ?
                    g_rd[pr] + (size_t)b * 2048 + g * 1024 + (m0 + nl0) : nullptr;
                const float* __restrict__ d1 = isES ? d0 + 512 : nullptr;
                float* __restrict__ rdw = isDend ?
                    g_rd[pw] + (size_t)b * 2048 + g * 1024 + (m0 - 512) + nl0 : nullptr;
                const int k0 = g * 896 + (m0 < 512 ? m0 : 512 + (m0 - 1536)) + nl0;
                bf16* __restrict__ rhw = g_rHi[pw] + (size_t)b * K_CMP + k0;
                bf16* __restrict__ rmw = g_rMi[pw] + (size_t)b * K_CMP + k0;
                #pragma unroll
                for (int i = 0; i < 8; i += 4) {
                    float4 hv = *(const float4*)&hp[i];
                    float4 nv = *(const float4*)&nz[i];
                    float tv[4], hn[4];
                    #pragma unroll
                    for (int j = 0; j < 4; j++)
                        tv[j] = dsm[(nl0 + i + j) * 72 + bl2] + bias_s[nl0 + i + j];
                    if (isES) {
                        float4 a0 = *(const float4*)&d0[i];
                        float4 a1 = *(const float4*)&d1[i];
                        tv[0] += a0.x + a1.x; tv[1] += a0.y + a1.y;
                        tv[2] += a0.z + a1.z; tv[3] += a0.w + a1.w;
                    }
                    hn[0] = 0.8f * hv.x + DECAY * tv[0] + NOISE_SCALE * nv.x;
                    hn[1] = 0.8f * hv.y + DECAY * tv[1] + NOISE_SCALE * nv.y;
                    hn[2] = 0.8f * hv.z + DECAY * tv[2] + NOISE_SCALE * nv.z;
                    hn[3] = 0.8f * hv.w + DECAY * tv[3] + NOISE_SCALE * nv.w;
                    *(float4*)&hp[i] = make_float4(hn[0], hn[1], hn[2], hn[3]);
                    if (isDend) {
                        *(float4*)&rdw[i] = make_float4(tanhf(hn[0]), tanhf(hn[1]),
                                                        tanhf(hn[2]), tanhf(hn[3]));
                    } else {
                        uint32_t hw[2], mw2[2];
                        #pragma unroll
                        for (int p = 0; p < 2; p++) {
                            float r0 = fmaxf(hn[p * 2], 0.f), r1 = fmaxf(hn[p * 2 + 1], 0.f);
                            bf16 h0b, m0b, h1b, m1b;
                            split2(r0, h0b, m0b);
                            split2(r1, h1b, m1b);
                            hw[p] = (uint32_t)__bfloat16_as_ushort(h0b) |
                                    ((uint32_t)__bfloat16_as_ushort(h1b) << 16);
                            mw2[p] = (uint32_t)__bfloat16_as_ushort(m0b) |
                                     ((uint32_t)__bfloat16_as_ushort(m1b) << 16);
                        }
                        *(uint2*)&rhw[i] = make_uint2(hw[0], hw[1]);
                        *(uint2*)&rmw[i] = make_uint2(mw2[0], mw2[1]);
                    }
                }
            }
            grid_barrier(gen); gen++;
        }
    } else {
        const int o = bx - NB_GEMM;
        float* wcol = (float*)sm;
        for (int s = tid; s < N_ES; s += NTHR) wcol[s] = w_out[(size_t)s * N_OUT + o];
        __syncthreads();
        for (int t = 0; t <= T_STEPS; t++) {
            if (t > 0 && tid < BATCH) {
                const int tt = t - 1, buf = (tt + 1) & 1;
                const uint4* __restrict__ rh =
                    (const uint4*)(g_rHi[buf] + (size_t)tid * K_CMP);
                const uint4* __restrict__ rm =
                    (const uint4*)(g_rMi[buf] + (size_t)tid * K_CMP);
                float acc = 0.f;
                #pragma unroll 4
                for (int v = 0; v < N_ES / 8; v++) {
                    uint4 ph = rh[v], pm = rm[v];
                    const bf16* eh = (const bf16*)&ph;
                    const bf16* em = (const bf16*)&pm;
                    #pragma unroll
                    for (int e = 0; e < 8; e++)
                        acc += (__bfloat162float(eh[e]) + __bfloat162float(em[e]))
                               * wcol[v * 8 + e];
                }
                out[((size_t)tt * BATCH + tid) * N_OUT + o] = acc;
            }
            if (t < T_STEPS) { grid_barrier(gen); gen++; }
        }
    }
}

extern "C" void kernel_launch(void* const* d_in, const int* in_sizes, int n_in,
                              void* d_out, int out_size) {
    const float* x     = (const float*)d_in[0];
    const float* noise = (const float*)d_in[1];
    const float* w_rec = (const float*)d_in[2];
    const float* w_in  = (const float*)d_in[3];
    const float* w_out = (const float*)d_in[4];
    const float* bias  = (const float*)d_in[5];
    const float* h0    = (const float*)d_in[6];
    const float* mask  = (const float*)d_in[7];
    float* out = (float*)d_out;
    (void)in_sizes; (void)n_in; (void)out_size;

    cudaFuncSetAttribute(rollout_kernel, cudaFuncAttributeMaxDynamicSharedMemorySize, SMEM_DYN);

    { dim3 g(K_CMP / 32, N_TOT / 32); prep_w_kernel<<<g, dim3(32, 8)>>>(w_rec, mask); }
    { size_t n = (size_t)N_IN * N_TOT; prep_win_kernel<<<(int)((n + 255) / 256), 256>>>(w_in); }
    { size_t n = (size_t)T_STEPS * BATCH * N_IN; prep_x_kernel<<<(int)((n + 255) / 256), 256>>>(x); }
    { size_t n = (size_t)BATCH * N_TOT; init_state_kernel<<<(int)((n + 255) / 256), 256>>>(h0); }
    reset_barrier_kernel<<<1, 1>>>();

    rollout_kernel<<<NBLK, NTHR, SMEM_DYN>>>(noise, bias, w_out, out);
}